// round 7
// baseline (speedup 1.0000x reference)
#include <cuda_runtime.h>
#include <math.h>

#define BATCH   128
#define DD      128
#define HH      256
#define NBLK_C  256
#define THREADS 1024
#define SEC     (BATCH*NBLK_C)
#define NGRP    16

typedef unsigned long long u64;

__device__ __align__(16) float g_E[BATCH * 511 * DD];
__device__ __align__(16) float g_BP[BATCH * 255 * HH];
__device__ int   g_X[BATCH * 511];
__device__ int   g_U1H[BATCH * 256];
__device__ int   g_fenc[BATCH * NBLK_C];
__device__ __align__(16) float g_Wf[256 * 512];   // [Wc1 | Wb1-top] col-fused
__device__ __align__(16) float g_bf[512];
__device__ __align__(16) float g_emb[2 * HH];
__device__ __align__(16) float g_w2l[512];
__device__ float g_pbias[2];
__device__ __align__(16) float g_gH[NGRP][64 * 256];  // group check-hidden exchange

__device__ __forceinline__ void fma2(u64& acc, u64 a, u64 b) {
    asm("fma.rn.f32x2 %0, %1, %2, %0;" : "+l"(acc) : "l"(a), "l"(b));
}
__device__ __forceinline__ u64 pk2(float x, float y) {
    u64 r; asm("mov.b64 %0, {%1, %2};" : "=l"(r) : "f"(x), "f"(y)); return r;
}
__device__ __forceinline__ float2 upk(u64 v) {
    float2 r; asm("mov.b64 {%0, %1}, %2;" : "=f"(r.x), "=f"(r.y) : "l"(v)); return r;
}
__device__ __forceinline__ void csync() {
    __threadfence();
    asm volatile("barrier.cluster.arrive.aligned;" ::: "memory");
    asm volatile("barrier.cluster.wait.aligned;" ::: "memory");
}

struct Ctx {
    float* Eb; float* BPb; int* Xb; int* U1Hb;
    u64* sWf; u64* stage; u64* hs; u64* redu; float* redf; int* nx;
    float* gH;
    const float* Wc2; const float* bc2;
    const float* Wb2; const float* bb2;
    const float* r_in;
    float* u_out; float* p_out;
    int b, rank, gb;
};

// ============ per-batch chunks (levels >= 5), weights streamed from L2 ============
template<int RB>
__device__ void l1_chunk(Ctx& c, const float* __restrict__ Ein, float* __restrict__ bp_out)
{
    const int t = threadIdx.x;
    u64* zs = c.stage; u64* hs = c.hs;
    for (int idx = t; idx < RB * 128; idx += THREADS) {
        float2 v = ((const float2*)Ein)[idx];
        ulonglong2 d; d.x = pk2(v.x, v.x); d.y = pk2(v.y, v.y);
        ((ulonglong2*)zs)[idx] = d;
    }
    __syncthreads();
    constexpr int NR = RB / 8;
    const int colq = t & 127;
    const int rg   = t >> 7;
    u64 acc[NR][2];
    #pragma unroll
    for (int r = 0; r < NR; r++) { acc[r][0] = 0ull; acc[r][1] = 0ull; }
    const ulonglong2* W = (const ulonglong2*)g_Wf + colq;
    #pragma unroll 2
    for (int k = 0; k < 256; k += 2) {
        ulonglong2 a2[NR];
        #pragma unroll
        for (int r = 0; r < NR; r++)
            a2[r] = *((const ulonglong2*)&zs[(rg + 8 * r) * 256 + k]);
        ulonglong2 w0 = __ldg(W + (size_t)k * 128);
        ulonglong2 w1 = __ldg(W + (size_t)(k + 1) * 128);
        #pragma unroll
        for (int r = 0; r < NR; r++) {
            fma2(acc[r][0], a2[r].x, w0.x); fma2(acc[r][1], a2[r].x, w0.y);
            fma2(acc[r][0], a2[r].y, w1.x); fma2(acc[r][1], a2[r].y, w1.y);
        }
    }
    const int col = colq * 4;
    float4 bias = *((const float4*)&g_bf[col]);
    #pragma unroll
    for (int r = 0; r < NR; r++) {
        int row = rg + 8 * r;
        float2 v0 = upk(acc[r][0]); float2 v1 = upk(acc[r][1]);
        float o0 = v0.x + bias.x, o1 = v0.y + bias.y;
        float o2 = v1.x + bias.z, o3 = v1.y + bias.w;
        if (col < 256) {
            float r0 = fmaxf(o0, 0.f), r1 = fmaxf(o1, 0.f);
            float r2 = fmaxf(o2, 0.f), r3 = fmaxf(o3, 0.f);
            ulonglong2 d0; d0.x = pk2(r0, r0); d0.y = pk2(r1, r1);
            ulonglong2 d1; d1.x = pk2(r2, r2); d1.y = pk2(r3, r3);
            *((ulonglong2*)&hs[row * 256 + col])     = d0;
            *((ulonglong2*)&hs[row * 256 + col + 2]) = d1;
        } else {
            *((float4*)&bp_out[row * HH + (col - 256)]) = make_float4(o0, o1, o2, o3);
        }
    }
    __syncthreads();
}

template<int RB>
__device__ void l2_chunk(Ctx& c, const float* __restrict__ W2,
                         const float* __restrict__ b2, float* __restrict__ Eout)
{
    const int t = threadIdx.x;
    const u64* hs = c.hs;
    const int colq = t & 31;
    const int g    = t >> 5;
    const ulonglong2* W = (const ulonglong2*)W2 + colq;
    if constexpr (RB == 32) {
        const int row = g;
        u64 acc0 = 0ull, acc1 = 0ull;
        #pragma unroll 2
        for (int k = 0; k < 256; k += 2) {
            ulonglong2 a2 = *((const ulonglong2*)&hs[row * 256 + k]);
            ulonglong2 w0 = __ldg(W + (size_t)k * 32);
            ulonglong2 w1 = __ldg(W + (size_t)(k + 1) * 32);
            fma2(acc0, a2.x, w0.x); fma2(acc1, a2.x, w0.y);
            fma2(acc0, a2.y, w1.x); fma2(acc1, a2.y, w1.y);
        }
        float2 v0 = upk(acc0), v1 = upk(acc1);
        const int col = colq * 4;
        float4 bb = *((const float4*)&b2[col]);
        *((float4*)&Eout[row * 128 + col]) =
            make_float4(v0.x + bb.x, v0.y + bb.y, v1.x + bb.z, v1.y + bb.w);
        __syncthreads();
    } else {  // RB == 16, split-K 2-way
        const int row = g & 15;
        const int kp  = g >> 4;
        const int k0  = kp * 128;
        u64 acc0 = 0ull, acc1 = 0ull;
        #pragma unroll 2
        for (int k = k0; k < k0 + 128; k += 2) {
            ulonglong2 a2 = *((const ulonglong2*)&hs[row * 256 + k]);
            ulonglong2 w0 = __ldg(W + (size_t)k * 32);
            ulonglong2 w1 = __ldg(W + (size_t)(k + 1) * 32);
            fma2(acc0, a2.x, w0.x); fma2(acc1, a2.x, w0.y);
            fma2(acc0, a2.y, w1.x); fma2(acc1, a2.y, w1.y);
        }
        float2 v0 = upk(acc0), v1 = upk(acc1);
        ((float4*)c.redf)[g * 32 + colq] = make_float4(v0.x, v0.y, v1.x, v1.y);
        __syncthreads();
        for (int idx = t; idx < 16 * 128; idx += THREADS) {
            int row2 = idx >> 7, col = idx & 127;
            float v = __ldg(&b2[col]) + c.redf[row2 * 128 + col] + c.redf[(16 + row2) * 128 + col];
            Eout[row2 * 128 + col] = v;
        }
        __syncthreads();
    }
}

__device__ void check_pb(Ctx& c, int l)
{
    const int half = 1 << (l - 1);
    const float* Ein = c.Eb + ((1 << l) - 1) * DD;
    float* Eout = c.Eb + (half - 1) * DD;
    float* BPl  = c.BPb + (half - 1) * HH;
    for (int done = 0; done < half; done += 32) {
        int rbc = half - done; if (rbc > 32) rbc = 32;
        if (rbc == 32) { l1_chunk<32>(c, Ein + done * 256, BPl + done * HH);
                         l2_chunk<32>(c, c.Wc2, c.bc2, Eout + done * DD); }
        else           { l1_chunk<16>(c, Ein + done * 256, BPl + done * HH);
                         l2_chunk<16>(c, c.Wc2, c.bc2, Eout + done * DD); }
    }
}

__device__ void bit_pb(Ctx& c, int l)
{
    const int half = 1 << (l - 1);
    const int base = half - 1;
    float* Eout = c.Eb + base * DD;
    const float* BPl = c.BPb + base * HH;
    int* u1h = c.U1Hb + base;
    int* Xlm = c.Xb + base;
    __syncthreads();
    for (int i = threadIdx.x; i < half; i += THREADS) u1h[i] = Xlm[i];
    __syncthreads();
    for (int done = 0; done < half; done += 32) {
        int rbc = half - done; if (rbc > 32) rbc = 32;
        for (int idx = threadIdx.x; idx < rbc * 256; idx += THREADS) {
            int row = idx >> 8, k = idx & 255;
            int u = u1h[done + row];
            float v = fmaxf(BPl[(done + row) * HH + k] + g_emb[u * HH + k], 0.f);
            c.hs[idx] = pk2(v, v);
        }
        __syncthreads();
        if (rbc == 32) l2_chunk<32>(c, c.Wb2, c.bb2, Eout + done * DD);
        else           l2_chunk<16>(c, c.Wb2, c.bb2, Eout + done * DD);
    }
}

// ============ cooperative chunks (levels <= 4): 8 CTAs, smem weight slices ============
// L1 fused [R32grp_rows x 256] @ [256 x 64slice]; check cols -> gH (relu), bp -> g_BP
template<int R32>
__device__ void coopL1(Ctx& c, int l, int cb)
{
    const int t = threadIdx.x;
    const int lr = l - 1;
    const int base = (1 << l) - 1;
    // stage acts (peer g_E via ldcg), dup f32x2
    for (int idx = t; idx < R32 * 128; idx += THREADS) {
        int r = idx >> 7, p2 = idx & 127;
        int gr = cb + r;
        int b = c.gb * 8 + (gr >> lr), rib = gr & ((1 << lr) - 1);
        float2 v = __ldcg((const float2*)(g_E + (size_t)b * 511 * DD + base * DD + rib * 256) + p2);
        ulonglong2 d; d.x = pk2(v.x, v.x); d.y = pk2(v.y, v.y);
        ((ulonglong2*)c.stage)[idx] = d;
    }
    __syncthreads();
    constexpr int SK = 64 / R32;
    constexpr int RGN = R32 / 2;
    const int colq = t & 31;
    const int rg   = (t >> 5) & (RGN - 1);
    const int kp   = t / (32 * RGN);
    const int kn   = 256 / SK;
    const int k0   = kp * kn;
    u64 a0 = 0ull, a1 = 0ull;
    const u64* Ws = c.sWf + (size_t)k0 * 32 + colq;
    const u64* A0 = c.stage + rg * 256 + k0;
    const u64* A1 = c.stage + (rg + RGN) * 256 + k0;
    #pragma unroll 4
    for (int k = 0; k < kn; k++) {
        u64 w = Ws[(size_t)k * 32];
        fma2(a0, A0[k], w);
        fma2(a1, A1[k], w);
    }
    c.redu[(kp * R32 + rg) * 32 + colq] = a0;
    c.redu[(kp * R32 + rg + RGN) * 32 + colq] = a1;
    __syncthreads();
    for (int it = t; it < R32 * 32; it += THREADS) {
        int r = it >> 5, cq = it & 31;
        float sx = 0.f, sy = 0.f;
        #pragma unroll
        for (int q = 0; q < SK; q++) {
            float2 v = upk(c.redu[(q * R32 + r) * 32 + cq]);
            sx += v.x; sy += v.y;
        }
        int col = (c.rank * 32 + cq) * 2;
        sx += g_bf[col]; sy += g_bf[col + 1];
        int gr = cb + r;
        if (col < 256) {
            float* dst = c.gH + gr * 256 + col;
            dst[0] = fmaxf(sx, 0.f); dst[1] = fmaxf(sy, 0.f);
        } else {
            int b = c.gb * 8 + (gr >> lr), rib = gr & ((1 << lr) - 1);
            int bpbase = (1 << lr) - 1;
            float* dst = g_BP + (size_t)b * 255 * HH + (bpbase + rib) * HH + (col - 256);
            dst[0] = sx; dst[1] = sy;
        }
    }
    __syncthreads();
}

// L2 [R32 x 256] @ [256 x 16slice]; hidden from gH (check) or relu(bp+emb[u1h]) (bit)
template<int R32>
__device__ void coopL2(Ctx& c, int l, int cb, bool isBit)
{
    const int t = threadIdx.x;
    const int lr = l - 1;
    const int bpbase = (1 << lr) - 1;
    const float* W2 = isBit ? c.Wb2 : c.Wc2;
    const float* b2 = isBit ? c.bb2 : c.bc2;
    for (int idx = t; idx < R32 * 128; idx += THREADS) {
        int r = idx >> 7, p2 = idx & 127;
        int gr = cb + r;
        float2 v;
        if (!isBit) {
            v = __ldcg((const float2*)(c.gH + gr * 256) + p2);
        } else {
            int b = c.gb * 8 + (gr >> lr), rib = gr & ((1 << lr) - 1);
            float2 bv = __ldcg((const float2*)(g_BP + (size_t)b * 255 * HH + (bpbase + rib) * HH) + p2);
            int u = __ldcg(g_U1H + b * 256 + bpbase + rib);
            float2 e = *((const float2*)(g_emb + u * HH) + p2);
            v.x = fmaxf(bv.x + e.x, 0.f); v.y = fmaxf(bv.y + e.y, 0.f);
        }
        ulonglong2 d; d.x = pk2(v.x, v.x); d.y = pk2(v.y, v.y);
        ((ulonglong2*)c.stage)[idx] = d;
    }
    __syncthreads();
    constexpr int KP = 128 / R32;
    const int colq = t & 7;
    const int row  = (t >> 3) & (R32 - 1);
    const int kp   = t / (8 * R32);
    const int kn   = 256 / KP;
    const int k0   = kp * kn;
    u64 acc = 0ull;
    const u64* W = (const u64*)W2 + c.rank * 8 + colq;
    const u64* A = c.stage + row * 256 + k0;
    #pragma unroll 8
    for (int k = 0; k < kn; k++)
        fma2(acc, A[k], __ldg(W + (size_t)(k0 + k) * 64));
    c.redu[(kp * R32 + row) * 8 + colq] = acc;
    __syncthreads();
    for (int it = t; it < R32 * 8; it += THREADS) {
        int r = it >> 3, cq = it & 7;
        float sx = 0.f, sy = 0.f;
        #pragma unroll
        for (int q = 0; q < KP; q++) {
            float2 v = upk(c.redu[(q * R32 + r) * 8 + cq]);
            sx += v.x; sy += v.y;
        }
        int col = (c.rank * 8 + cq) * 2;
        sx += __ldg(&b2[col]); sy += __ldg(&b2[col + 1]);
        int gr = cb + r;
        int b = c.gb * 8 + (gr >> lr), rib = gr & ((1 << lr) - 1);
        float* dst = g_E + (size_t)b * 511 * DD + (bpbase + rib) * DD + col;
        dst[0] = sx; dst[1] = sy;
    }
    __syncthreads();
}

__device__ void check_coop(Ctx& c, int l)
{
    if (l == 4) {
        csync();  // per-batch -> coop transition: peers' E level-4 must be visible
        coopL1<32>(c, 4, 0);  coopL1<32>(c, 4, 32);
        csync();
        coopL2<32>(c, 4, 0, false); coopL2<32>(c, 4, 32, false);
        csync();
    } else if (l == 3) {
        coopL1<32>(c, 3, 0);
        csync();
        coopL2<32>(c, 3, 0, false);
        csync();
    } else {
        coopL1<16>(c, 2, 0);
        csync();
        coopL2<16>(c, 2, 0, false);
        csync();
    }
}

__device__ void bit_coop(Ctx& c, int l)
{
    const int R = 1 << (l - 1), base = R - 1;
    __syncthreads();
    for (int i = threadIdx.x; i < R; i += THREADS) c.U1Hb[base + i] = c.Xb[base + i];
    csync();  // publish u1h
    if (l == 4)      { coopL2<32>(c, 4, 0, true); coopL2<32>(c, 4, 32, true); }
    else if (l == 3)   coopL2<32>(c, 3, 0, true);
    else               coopL2<16>(c, 2, 0, true);
    csync();
}

__device__ __forceinline__ void combine_stage(Ctx& c, int l)
{
    int half = 1 << (l - 1);
    int* u1h = c.U1Hb + (half - 1);
    int* Xlm = c.Xb + (half - 1);
    int* Xl  = c.Xb + ((1 << l) - 1);
    __syncthreads();
    for (int i = threadIdx.x; i < half; i += THREADS) {
        int u2 = Xlm[i];
        Xl[2 * i]     = u1h[i] ^ u2;
        Xl[2 * i + 1] = u2;
    }
    __syncthreads();
}

// level-1 node: coop L1 (GR=8) then per-batch dots vs precomputed W2@Wl
__device__ void node1(Ctx& c, int n)
{
    coopL1<8>(c, 1, 0);
    csync();
    const int t = threadIdx.x;
    if (t < 32) {
        float s = 0.f;
        #pragma unroll
        for (int j = 0; j < 8; j++) {
            int idx = t + 32 * j;
            s = fmaf(__ldcg(c.gH + c.rank * 256 + idx), g_w2l[idx], s);
        }
        #pragma unroll
        for (int o = 16; o > 0; o >>= 1) s += __shfl_xor_sync(0xffffffffu, s, o);
        if (t == 0) {
            float p = 1.f / (1.f + expf(-(s + g_pbias[0])));
            int leaf = 2 * n;
            float rv = __ldg(&c.r_in[c.b * NBLK_C + leaf]);
            int f  = g_fenc[c.b * NBLK_C + leaf];
            int hd = (rv > p) ? 1 : 0;
            int x  = ((f == 2) || (fabsf(p - 0.5f) > 0.25f)) ? hd : f;
            *c.nx = x;
            c.u_out[c.b * NBLK_C + leaf] = (float)x;
            c.p_out[c.b * NBLK_C + leaf] = p;
        }
    }
    __syncthreads();
    int xL = *c.nx;
    if (t < 32) {
        float s = 0.f;
        #pragma unroll
        for (int j = 0; j < 8; j++) {
            int idx = t + 32 * j;
            float bp = __ldcg(c.BPb + idx);   // level-1 bp = row 0
            float h = fmaxf(bp + g_emb[xL * HH + idx], 0.f);
            s = fmaf(h, g_w2l[256 + idx], s);
        }
        #pragma unroll
        for (int o = 16; o > 0; o >>= 1) s += __shfl_xor_sync(0xffffffffu, s, o);
        if (t == 0) {
            float p = 1.f / (1.f + expf(-(s + g_pbias[1])));
            int leaf = 2 * n + 1;
            float rv = __ldg(&c.r_in[c.b * NBLK_C + leaf]);
            int f  = g_fenc[c.b * NBLK_C + leaf];
            int hd = (rv > p) ? 1 : 0;
            int xR = ((f == 2) || (fabsf(p - 0.5f) > 0.25f)) ? hd : f;
            c.u_out[c.b * NBLK_C + leaf] = (float)xR;
            c.p_out[c.b * NBLK_C + leaf] = p;
            c.Xb[1] = xL ^ xR;
            c.Xb[2] = xR;
        }
    }
    __syncthreads();
}

__global__ void __launch_bounds__(THREADS, 1) __cluster_dims__(8, 1, 1)
sc_main(const float* r_in,
        const float* Wc2, const float* bc2,
        const float* Wb2, const float* bb2,
        float* out)
{
    extern __shared__ __align__(16) char smraw[];
    Ctx c;
    c.sWf   = (u64*)smraw;          // 64 KB: Wf column slice
    c.stage = c.sWf + 8192;         // 64 KB: act staging / per-batch zs
    c.hs    = c.stage + 8192;       // 64 KB: per-batch hidden
    c.redu  = c.hs + 8192;          // 16 KB
    c.redf  = (float*)c.redu;
    c.nx    = (int*)(c.redu + 2048);
    c.b = blockIdx.x; c.rank = c.b & 7; c.gb = c.b >> 3;
    c.gH   = g_gH[c.gb];
    c.Eb   = g_E   + (size_t)c.b * 511 * DD;
    c.BPb  = g_BP  + (size_t)c.b * 255 * HH;
    c.Xb   = g_X   + c.b * 511;
    c.U1Hb = g_U1H + c.b * 256;
    c.Wc2 = Wc2; c.bc2 = bc2; c.Wb2 = Wb2; c.bb2 = bb2;
    c.r_in  = r_in;
    c.u_out = out + 2 * SEC;
    c.p_out = out + 3 * SEC;

    // load this CTA's Wf column slice into smem (once)
    {
        const u64* src = (const u64*)g_Wf;
        for (int i = threadIdx.x; i < 8192; i += THREADS) {
            int k = i >> 5, cq = i & 31;
            c.sWf[i] = __ldg(src + (size_t)k * 256 + c.rank * 32 + cq);
        }
    }
    __syncthreads();

    for (int l = 8; l >= 5; l--) check_pb(c, l);
    for (int l = 4; l >= 2; l--) check_coop(c, l);
    for (int n = 0; n < 128; n++) {
        node1(c, n);
        if (n == 127) break;
        int l = 2;
        while ((n >> (l - 2)) & 1) { combine_stage(c, l); l++; }
        if (l >= 5) bit_pb(c, l); else bit_coop(c, l);
        for (int ld = l - 1; ld >= 5; ld--) check_pb(c, ld);
        int top = (l - 1 < 4) ? l - 1 : 4;
        for (int ld = top; ld >= 2; ld--) check_coop(c, ld);
    }
    for (int l = 2; l <= 8; l++) combine_stage(c, l);

    int* X8 = c.Xb + 255;
    for (int i = threadIdx.x; i < NBLK_C; i += THREADS)
        out[c.b * NBLK_C + i] = (float)X8[i];
}

// ---- per-batch init ----
__global__ void sc_setup(const int* info_bits, const float* r_in, const int* info_set,
                         const float* E_obs, float* out)
{
    int b = blockIdx.x, t = threadIdx.x;
    for (int j = t; j < NBLK_C; j += blockDim.x) {
        g_fenc[b * NBLK_C + j] = 2;
        out[1 * SEC + b * NBLK_C + j] = 1.0f;
        out[4 * SEC + b * NBLK_C + j] = r_in[b * NBLK_C + j];
    }
    __syncthreads();
    for (int k = t; k < 128; k += blockDim.x) {
        int pos = info_set[k];
        g_fenc[b * NBLK_C + pos] = info_bits[b * 128 + k];
        out[1 * SEC + b * NBLK_C + pos] = 2.0f;
    }
    for (int idx = t; idx < 256 * DD; idx += blockDim.x) {
        int i = idx >> 7, k = idx & (DD - 1);
        g_E[(size_t)b * 511 * DD + (255 + i) * DD + k] = E_obs[2 * DD + k];
    }
}

// ---- parallel weight prep ----
__global__ void sc_prep(const float* Wc1, const float* bc1,
                        const float* Wb1, const float* bb1,
                        const float* E_lab,
                        const float* Wc2, const float* bc2,
                        const float* Wb2, const float* bb2,
                        const float* Wl, const float* bl)
{
    int tid = blockIdx.x * blockDim.x + threadIdx.x;   // 64*512
    {
        int k = tid >> 7, c4 = (tid & 127) * 4;
        float4 v;
        if (c4 < 256) v = *((const float4*)&Wc1[k * 256 + c4]);
        else          v = *((const float4*)&Wb1[k * 256 + (c4 - 256)]);
        *((float4*)&g_Wf[k * 512 + c4]) = v;
    }
    if (tid < 512) g_bf[tid] = (tid < 256) ? bc1[tid] : bb1[tid - 256];
    if (tid >= 512 && tid < 1024) {
        int cidx = tid - 512;
        const float* W2 = (cidx < 256) ? Wc2 : Wb2;
        int k = cidx & 255;
        float s = 0.f;
        for (int d = 0; d < 128; d++) s += W2[k * 128 + d] * Wl[d];
        g_w2l[cidx] = s;
    }
    if (tid >= 1024 && tid < 1536) {
        int cidx = tid - 1024; int u = cidx >> 8, j = cidx & 255;
        float s = 0.f;
        for (int d = 0; d < 128; d++) s += E_lab[u * 128 + d] * Wb1[(256 + d) * 256 + j];
        g_emb[u * HH + j] = s;
    }
    if (tid == 1536 || tid == 1537) {
        int u = tid - 1536;
        const float* b2 = u ? bb2 : bc2;
        float s = bl[0];
        for (int d = 0; d < 128; d++) s += b2[d] * Wl[d];
        g_pbias[u] = s;
    }
}

extern "C" void kernel_launch(void* const* d_in, const int* in_sizes, int n_in,
                              void* d_out, int out_size)
{
    const int*   info_bits = (const int*)  d_in[0];
    const float* r_in      = (const float*)d_in[1];
    const int*   info_set  = (const int*)  d_in[2];
    const float* E_obs     = (const float*)d_in[3];
    const float* E_lab     = (const float*)d_in[4];
    const float* Wc1 = (const float*)d_in[5];
    const float* bc1 = (const float*)d_in[6];
    const float* Wc2 = (const float*)d_in[7];
    const float* bc2 = (const float*)d_in[8];
    const float* Wb1 = (const float*)d_in[9];
    const float* bb1 = (const float*)d_in[10];
    const float* Wb2 = (const float*)d_in[11];
    const float* bb2 = (const float*)d_in[12];
    const float* Wl  = (const float*)d_in[13];
    const float* bl  = (const float*)d_in[14];
    float* out = (float*)d_out;

    const int smem = (8192 * 3 + 2048) * 8 + 64;   // ~208 KB
    cudaFuncSetAttribute(sc_main, cudaFuncAttributeMaxDynamicSharedMemorySize, smem);

    sc_prep<<<64, 512>>>(Wc1, bc1, Wb1, bb1, E_lab, Wc2, bc2, Wb2, bb2, Wl, bl);
    sc_setup<<<BATCH, 256>>>(info_bits, r_in, info_set, E_obs, out);
    sc_main<<<BATCH, THREADS, smem>>>(r_in, Wc2, bc2, Wb2, bb2, out);
}

// round 8
// speedup vs baseline: 1.0019x; 1.0019x over previous
#include <cuda_runtime.h>
#include <math.h>

#define BATCH   128
#define DD      128
#define HH      256
#define NBLK_C  256
#define THREADS 1024
#define SEC     (BATCH*NBLK_C)
#define NGRP    16

typedef unsigned long long u64;

__device__ __align__(16) float g_E[BATCH * 511 * DD];
__device__ __align__(16) float g_BP[BATCH * 255 * HH];
__device__ int   g_X[BATCH * 511];
__device__ int   g_U1H[BATCH * 256];
__device__ int   g_fenc[BATCH * NBLK_C];
__device__ __align__(16) float g_Wf[256 * 512];   // [Wc1 | Wb1-top] col-fused
__device__ __align__(16) float g_bf[512];
__device__ __align__(16) float g_emb[2 * HH];
__device__ __align__(16) float g_w2l[512];
__device__ float g_pbias[2];
__device__ __align__(16) float g_gH[NGRP][64 * 256];  // group check-hidden exchange

__device__ __forceinline__ void fma2(u64& acc, u64 a, u64 b) {
    asm("fma.rn.f32x2 %0, %1, %2, %0;" : "+l"(acc) : "l"(a), "l"(b));
}
__device__ __forceinline__ u64 pk2(float x, float y) {
    u64 r; asm("mov.b64 %0, {%1, %2};" : "=l"(r) : "f"(x), "f"(y)); return r;
}
__device__ __forceinline__ float2 upk(u64 v) {
    float2 r; asm("mov.b64 {%0, %1}, %2;" : "=f"(r.x), "=f"(r.y) : "l"(v)); return r;
}
// cluster-scope fence + cluster barrier (arrive=release, wait=acquire).
// NO gpu-scope threadfence: that was the R7 regression.
__device__ __forceinline__ void csync() {
    asm volatile("fence.acq_rel.cluster;" ::: "memory");
    asm volatile("barrier.cluster.arrive.aligned;" ::: "memory");
    asm volatile("barrier.cluster.wait.aligned;" ::: "memory");
}

struct Ctx {
    float* Eb; float* BPb; int* Xb; int* U1Hb;
    u64* sWf; u64* stage; u64* hs; u64* redu; float* redf; int* nx;
    float* gH;
    const float* Wc2; const float* bc2;
    const float* Wb2; const float* bb2;
    const float* r_in;
    float* u_out; float* p_out;
    int b, rank, gb;
};

// ============ per-batch chunks (levels >= 5), weights streamed from L2 ============
template<int RB>
__device__ void l1_chunk(Ctx& c, const float* __restrict__ Ein, float* __restrict__ bp_out)
{
    const int t = threadIdx.x;
    u64* zs = c.stage; u64* hs = c.hs;
    for (int idx = t; idx < RB * 128; idx += THREADS) {
        float2 v = ((const float2*)Ein)[idx];
        ulonglong2 d; d.x = pk2(v.x, v.x); d.y = pk2(v.y, v.y);
        ((ulonglong2*)zs)[idx] = d;
    }
    __syncthreads();
    constexpr int NR = RB / 8;
    const int colq = t & 127;
    const int rg   = t >> 7;
    u64 acc[NR][2];
    #pragma unroll
    for (int r = 0; r < NR; r++) { acc[r][0] = 0ull; acc[r][1] = 0ull; }
    const ulonglong2* W = (const ulonglong2*)g_Wf + colq;
    #pragma unroll 2
    for (int k = 0; k < 256; k += 2) {
        ulonglong2 a2[NR];
        #pragma unroll
        for (int r = 0; r < NR; r++)
            a2[r] = *((const ulonglong2*)&zs[(rg + 8 * r) * 256 + k]);
        ulonglong2 w0 = __ldg(W + (size_t)k * 128);
        ulonglong2 w1 = __ldg(W + (size_t)(k + 1) * 128);
        #pragma unroll
        for (int r = 0; r < NR; r++) {
            fma2(acc[r][0], a2[r].x, w0.x); fma2(acc[r][1], a2[r].x, w0.y);
            fma2(acc[r][0], a2[r].y, w1.x); fma2(acc[r][1], a2[r].y, w1.y);
        }
    }
    const int col = colq * 4;
    float4 bias = *((const float4*)&g_bf[col]);
    #pragma unroll
    for (int r = 0; r < NR; r++) {
        int row = rg + 8 * r;
        float2 v0 = upk(acc[r][0]); float2 v1 = upk(acc[r][1]);
        float o0 = v0.x + bias.x, o1 = v0.y + bias.y;
        float o2 = v1.x + bias.z, o3 = v1.y + bias.w;
        if (col < 256) {
            float r0 = fmaxf(o0, 0.f), r1 = fmaxf(o1, 0.f);
            float r2 = fmaxf(o2, 0.f), r3 = fmaxf(o3, 0.f);
            ulonglong2 d0; d0.x = pk2(r0, r0); d0.y = pk2(r1, r1);
            ulonglong2 d1; d1.x = pk2(r2, r2); d1.y = pk2(r3, r3);
            *((ulonglong2*)&hs[row * 256 + col])     = d0;
            *((ulonglong2*)&hs[row * 256 + col + 2]) = d1;
        } else {
            *((float4*)&bp_out[row * HH + (col - 256)]) = make_float4(o0, o1, o2, o3);
        }
    }
    __syncthreads();
}

template<int RB>
__device__ void l2_chunk(Ctx& c, const float* __restrict__ W2,
                         const float* __restrict__ b2, float* __restrict__ Eout)
{
    const int t = threadIdx.x;
    const u64* hs = c.hs;
    const int colq = t & 31;
    const int g    = t >> 5;
    const ulonglong2* W = (const ulonglong2*)W2 + colq;
    if constexpr (RB == 32) {
        const int row = g;
        u64 acc0 = 0ull, acc1 = 0ull;
        #pragma unroll 2
        for (int k = 0; k < 256; k += 2) {
            ulonglong2 a2 = *((const ulonglong2*)&hs[row * 256 + k]);
            ulonglong2 w0 = __ldg(W + (size_t)k * 32);
            ulonglong2 w1 = __ldg(W + (size_t)(k + 1) * 32);
            fma2(acc0, a2.x, w0.x); fma2(acc1, a2.x, w0.y);
            fma2(acc0, a2.y, w1.x); fma2(acc1, a2.y, w1.y);
        }
        float2 v0 = upk(acc0), v1 = upk(acc1);
        const int col = colq * 4;
        float4 bb = *((const float4*)&b2[col]);
        *((float4*)&Eout[row * 128 + col]) =
            make_float4(v0.x + bb.x, v0.y + bb.y, v1.x + bb.z, v1.y + bb.w);
        __syncthreads();
    } else {  // RB == 16, split-K 2-way
        const int row = g & 15;
        const int kp  = g >> 4;
        const int k0  = kp * 128;
        u64 acc0 = 0ull, acc1 = 0ull;
        #pragma unroll 2
        for (int k = k0; k < k0 + 128; k += 2) {
            ulonglong2 a2 = *((const ulonglong2*)&hs[row * 256 + k]);
            ulonglong2 w0 = __ldg(W + (size_t)k * 32);
            ulonglong2 w1 = __ldg(W + (size_t)(k + 1) * 32);
            fma2(acc0, a2.x, w0.x); fma2(acc1, a2.x, w0.y);
            fma2(acc0, a2.y, w1.x); fma2(acc1, a2.y, w1.y);
        }
        float2 v0 = upk(acc0), v1 = upk(acc1);
        ((float4*)c.redf)[g * 32 + colq] = make_float4(v0.x, v0.y, v1.x, v1.y);
        __syncthreads();
        for (int idx = t; idx < 16 * 128; idx += THREADS) {
            int row2 = idx >> 7, col = idx & 127;
            float v = __ldg(&b2[col]) + c.redf[row2 * 128 + col] + c.redf[(16 + row2) * 128 + col];
            Eout[row2 * 128 + col] = v;
        }
        __syncthreads();
    }
}

__device__ void check_pb(Ctx& c, int l)
{
    const int half = 1 << (l - 1);
    const float* Ein = c.Eb + ((1 << l) - 1) * DD;
    float* Eout = c.Eb + (half - 1) * DD;
    float* BPl  = c.BPb + (half - 1) * HH;
    for (int done = 0; done < half; done += 32) {
        int rbc = half - done; if (rbc > 32) rbc = 32;
        if (rbc == 32) { l1_chunk<32>(c, Ein + done * 256, BPl + done * HH);
                         l2_chunk<32>(c, c.Wc2, c.bc2, Eout + done * DD); }
        else           { l1_chunk<16>(c, Ein + done * 256, BPl + done * HH);
                         l2_chunk<16>(c, c.Wc2, c.bc2, Eout + done * DD); }
    }
}

__device__ void bit_pb(Ctx& c, int l)
{
    const int half = 1 << (l - 1);
    const int base = half - 1;
    float* Eout = c.Eb + base * DD;
    const float* BPl = c.BPb + base * HH;
    int* u1h = c.U1Hb + base;
    int* Xlm = c.Xb + base;
    __syncthreads();
    for (int i = threadIdx.x; i < half; i += THREADS) u1h[i] = Xlm[i];
    __syncthreads();
    for (int done = 0; done < half; done += 32) {
        int rbc = half - done; if (rbc > 32) rbc = 32;
        for (int idx = threadIdx.x; idx < rbc * 256; idx += THREADS) {
            int row = idx >> 8, k = idx & 255;
            int u = u1h[done + row];
            float v = fmaxf(BPl[(done + row) * HH + k] + g_emb[u * HH + k], 0.f);
            c.hs[idx] = pk2(v, v);
        }
        __syncthreads();
        if (rbc == 32) l2_chunk<32>(c, c.Wb2, c.bb2, Eout + done * DD);
        else           l2_chunk<16>(c, c.Wb2, c.bb2, Eout + done * DD);
    }
}

// ============ cooperative chunks (levels <= 4): 8 CTAs, smem weight slices ============
template<int R32>
__device__ void coopL1(Ctx& c, int l, int cb)
{
    const int t = threadIdx.x;
    const int lr = l - 1;
    const int base = (1 << l) - 1;
    for (int idx = t; idx < R32 * 128; idx += THREADS) {
        int r = idx >> 7, p2 = idx & 127;
        int gr = cb + r;
        int b = c.gb * 8 + (gr >> lr), rib = gr & ((1 << lr) - 1);
        float2 v = __ldcg((const float2*)(g_E + (size_t)b * 511 * DD + base * DD + rib * 256) + p2);
        ulonglong2 d; d.x = pk2(v.x, v.x); d.y = pk2(v.y, v.y);
        ((ulonglong2*)c.stage)[idx] = d;
    }
    __syncthreads();
    constexpr int SK = 64 / R32;
    constexpr int RGN = R32 / 2;
    const int colq = t & 31;
    const int rg   = (t >> 5) & (RGN - 1);
    const int kp   = t / (32 * RGN);
    const int kn   = 256 / SK;
    const int k0   = kp * kn;
    u64 a0 = 0ull, a1 = 0ull;
    const u64* Ws = c.sWf + (size_t)k0 * 32 + colq;
    const u64* A0 = c.stage + rg * 256 + k0;
    const u64* A1 = c.stage + (rg + RGN) * 256 + k0;
    #pragma unroll 4
    for (int k = 0; k < kn; k++) {
        u64 w = Ws[(size_t)k * 32];
        fma2(a0, A0[k], w);
        fma2(a1, A1[k], w);
    }
    c.redu[(kp * R32 + rg) * 32 + colq] = a0;
    c.redu[(kp * R32 + rg + RGN) * 32 + colq] = a1;
    __syncthreads();
    for (int it = t; it < R32 * 32; it += THREADS) {
        int r = it >> 5, cq = it & 31;
        float sx = 0.f, sy = 0.f;
        #pragma unroll
        for (int q = 0; q < SK; q++) {
            float2 v = upk(c.redu[(q * R32 + r) * 32 + cq]);
            sx += v.x; sy += v.y;
        }
        int col = (c.rank * 32 + cq) * 2;
        sx += g_bf[col]; sy += g_bf[col + 1];
        int gr = cb + r;
        if (col < 256) {
            __stcg((float2*)(c.gH + gr * 256 + col), make_float2(fmaxf(sx, 0.f), fmaxf(sy, 0.f)));
        } else {
            int b = c.gb * 8 + (gr >> lr), rib = gr & ((1 << lr) - 1);
            int bpbase = (1 << lr) - 1;
            __stcg((float2*)(g_BP + (size_t)b * 255 * HH + (bpbase + rib) * HH + (col - 256)),
                   make_float2(sx, sy));
        }
    }
    __syncthreads();
}

template<int R32>
__device__ void coopL2(Ctx& c, int l, int cb, bool isBit)
{
    const int t = threadIdx.x;
    const int lr = l - 1;
    const int bpbase = (1 << lr) - 1;
    const float* W2 = isBit ? c.Wb2 : c.Wc2;
    const float* b2 = isBit ? c.bb2 : c.bc2;
    for (int idx = t; idx < R32 * 128; idx += THREADS) {
        int r = idx >> 7, p2 = idx & 127;
        int gr = cb + r;
        float2 v;
        if (!isBit) {
            v = __ldcg((const float2*)(c.gH + gr * 256) + p2);
        } else {
            int b = c.gb * 8 + (gr >> lr), rib = gr & ((1 << lr) - 1);
            float2 bv = __ldcg((const float2*)(g_BP + (size_t)b * 255 * HH + (bpbase + rib) * HH) + p2);
            int u = __ldcg(g_U1H + b * 256 + bpbase + rib);
            float2 e = *((const float2*)(g_emb + u * HH) + p2);
            v.x = fmaxf(bv.x + e.x, 0.f); v.y = fmaxf(bv.y + e.y, 0.f);
        }
        ulonglong2 d; d.x = pk2(v.x, v.x); d.y = pk2(v.y, v.y);
        ((ulonglong2*)c.stage)[idx] = d;
    }
    __syncthreads();
    constexpr int KP = 128 / R32;
    const int colq = t & 7;
    const int row  = (t >> 3) & (R32 - 1);
    const int kp   = t / (8 * R32);
    const int kn   = 256 / KP;
    const int k0   = kp * kn;
    u64 acc = 0ull;
    const u64* W = (const u64*)W2 + c.rank * 8 + colq;
    const u64* A = c.stage + row * 256 + k0;
    #pragma unroll 8
    for (int k = 0; k < kn; k++)
        fma2(acc, A[k], __ldg(W + (size_t)(k0 + k) * 64));
    c.redu[(kp * R32 + row) * 8 + colq] = acc;
    __syncthreads();
    for (int it = t; it < R32 * 8; it += THREADS) {
        int r = it >> 3, cq = it & 7;
        float sx = 0.f, sy = 0.f;
        #pragma unroll
        for (int q = 0; q < KP; q++) {
            float2 v = upk(c.redu[(q * R32 + r) * 8 + cq]);
            sx += v.x; sy += v.y;
        }
        int col = (c.rank * 8 + cq) * 2;
        sx += __ldg(&b2[col]); sy += __ldg(&b2[col + 1]);
        int gr = cb + r;
        int b = c.gb * 8 + (gr >> lr), rib = gr & ((1 << lr) - 1);
        __stcg((float2*)(g_E + (size_t)b * 511 * DD + (bpbase + rib) * DD + col),
               make_float2(sx, sy));
    }
    __syncthreads();
}

__device__ void check_coop(Ctx& c, int l)
{
    if (l == 4) {
        csync();
        coopL1<32>(c, 4, 0);  coopL1<32>(c, 4, 32);
        csync();
        coopL2<32>(c, 4, 0, false); coopL2<32>(c, 4, 32, false);
        csync();
    } else if (l == 3) {
        coopL1<32>(c, 3, 0);
        csync();
        coopL2<32>(c, 3, 0, false);
        csync();
    } else {
        coopL1<16>(c, 2, 0);
        csync();
        coopL2<16>(c, 2, 0, false);
        csync();
    }
}

__device__ void bit_coop(Ctx& c, int l)
{
    const int R = 1 << (l - 1), base = R - 1;
    __syncthreads();
    for (int i = threadIdx.x; i < R; i += THREADS)
        __stcg(c.U1Hb + base + i, c.Xb[base + i]);
    csync();
    if (l == 4)      { coopL2<32>(c, 4, 0, true); coopL2<32>(c, 4, 32, true); }
    else if (l == 3)   coopL2<32>(c, 3, 0, true);
    else               coopL2<16>(c, 2, 0, true);
    csync();
}

__device__ __forceinline__ void combine_stage(Ctx& c, int l)
{
    int half = 1 << (l - 1);
    int* u1h = c.U1Hb + (half - 1);
    int* Xlm = c.Xb + (half - 1);
    int* Xl  = c.Xb + ((1 << l) - 1);
    __syncthreads();
    for (int i = threadIdx.x; i < half; i += THREADS) {
        int u2 = Xlm[i];
        Xl[2 * i]     = u1h[i] ^ u2;
        Xl[2 * i + 1] = u2;
    }
    __syncthreads();
}

__device__ void node1(Ctx& c, int n)
{
    coopL1<8>(c, 1, 0);
    csync();
    const int t = threadIdx.x;
    if (t < 32) {
        float s = 0.f;
        #pragma unroll
        for (int j = 0; j < 8; j++) {
            int idx = t + 32 * j;
            s = fmaf(__ldcg(c.gH + c.rank * 256 + idx), g_w2l[idx], s);
        }
        #pragma unroll
        for (int o = 16; o > 0; o >>= 1) s += __shfl_xor_sync(0xffffffffu, s, o);
        if (t == 0) {
            float p = 1.f / (1.f + expf(-(s + g_pbias[0])));
            int leaf = 2 * n;
            float rv = __ldg(&c.r_in[c.b * NBLK_C + leaf]);
            int f  = g_fenc[c.b * NBLK_C + leaf];
            int hd = (rv > p) ? 1 : 0;
            int x  = ((f == 2) || (fabsf(p - 0.5f) > 0.25f)) ? hd : f;
            *c.nx = x;
            c.u_out[c.b * NBLK_C + leaf] = (float)x;
            c.p_out[c.b * NBLK_C + leaf] = p;
        }
    }
    __syncthreads();
    int xL = *c.nx;
    if (t < 32) {
        float s = 0.f;
        #pragma unroll
        for (int j = 0; j < 8; j++) {
            int idx = t + 32 * j;
            float bp = __ldcg(c.BPb + idx);
            float h = fmaxf(bp + g_emb[xL * HH + idx], 0.f);
            s = fmaf(h, g_w2l[256 + idx], s);
        }
        #pragma unroll
        for (int o = 16; o > 0; o >>= 1) s += __shfl_xor_sync(0xffffffffu, s, o);
        if (t == 0) {
            float p = 1.f / (1.f + expf(-(s + g_pbias[1])));
            int leaf = 2 * n + 1;
            float rv = __ldg(&c.r_in[c.b * NBLK_C + leaf]);
            int f  = g_fenc[c.b * NBLK_C + leaf];
            int hd = (rv > p) ? 1 : 0;
            int xR = ((f == 2) || (fabsf(p - 0.5f) > 0.25f)) ? hd : f;
            c.u_out[c.b * NBLK_C + leaf] = (float)xR;
            c.p_out[c.b * NBLK_C + leaf] = p;
            c.Xb[1] = xL ^ xR;
            c.Xb[2] = xR;
        }
    }
    __syncthreads();
}

__global__ void __launch_bounds__(THREADS, 1) __cluster_dims__(8, 1, 1)
sc_main(const float* r_in,
        const float* Wc2, const float* bc2,
        const float* Wb2, const float* bb2,
        float* out)
{
    extern __shared__ __align__(16) char smraw[];
    Ctx c;
    c.sWf   = (u64*)smraw;
    c.stage = c.sWf + 8192;
    c.hs    = c.stage + 8192;
    c.redu  = c.hs + 8192;
    c.redf  = (float*)c.redu;
    c.nx    = (int*)(c.redu + 2048);
    c.b = blockIdx.x; c.rank = c.b & 7; c.gb = c.b >> 3;
    c.gH   = g_gH[c.gb];
    c.Eb   = g_E   + (size_t)c.b * 511 * DD;
    c.BPb  = g_BP  + (size_t)c.b * 255 * HH;
    c.Xb   = g_X   + c.b * 511;
    c.U1Hb = g_U1H + c.b * 256;
    c.Wc2 = Wc2; c.bc2 = bc2; c.Wb2 = Wb2; c.bb2 = bb2;
    c.r_in  = r_in;
    c.u_out = out + 2 * SEC;
    c.p_out = out + 3 * SEC;

    {
        const u64* src = (const u64*)g_Wf;
        for (int i = threadIdx.x; i < 8192; i += THREADS) {
            int k = i >> 5, cq = i & 31;
            c.sWf[i] = __ldg(src + (size_t)k * 256 + c.rank * 32 + cq);
        }
    }
    __syncthreads();

    for (int l = 8; l >= 5; l--) check_pb(c, l);
    for (int l = 4; l >= 2; l--) check_coop(c, l);
    for (int n = 0; n < 128; n++) {
        node1(c, n);
        if (n == 127) break;
        int l = 2;
        while ((n >> (l - 2)) & 1) { combine_stage(c, l); l++; }
        if (l >= 5) bit_pb(c, l); else bit_coop(c, l);
        for (int ld = l - 1; ld >= 5; ld--) check_pb(c, ld);
        int top = (l - 1 < 4) ? l - 1 : 4;
        for (int ld = top; ld >= 2; ld--) check_coop(c, ld);
    }
    for (int l = 2; l <= 8; l++) combine_stage(c, l);

    int* X8 = c.Xb + 255;
    for (int i = threadIdx.x; i < NBLK_C; i += THREADS)
        out[c.b * NBLK_C + i] = (float)X8[i];
}

__global__ void sc_setup(const int* info_bits, const float* r_in, const int* info_set,
                         const float* E_obs, float* out)
{
    int b = blockIdx.x, t = threadIdx.x;
    for (int j = t; j < NBLK_C; j += blockDim.x) {
        g_fenc[b * NBLK_C + j] = 2;
        out[1 * SEC + b * NBLK_C + j] = 1.0f;
        out[4 * SEC + b * NBLK_C + j] = r_in[b * NBLK_C + j];
    }
    __syncthreads();
    for (int k = t; k < 128; k += blockDim.x) {
        int pos = info_set[k];
        g_fenc[b * NBLK_C + pos] = info_bits[b * 128 + k];
        out[1 * SEC + b * NBLK_C + pos] = 2.0f;
    }
    for (int idx = t; idx < 256 * DD; idx += blockDim.x) {
        int i = idx >> 7, k = idx & (DD - 1);
        g_E[(size_t)b * 511 * DD + (255 + i) * DD + k] = E_obs[2 * DD + k];
    }
}

__global__ void sc_prep(const float* Wc1, const float* bc1,
                        const float* Wb1, const float* bb1,
                        const float* E_lab,
                        const float* Wc2, const float* bc2,
                        const float* Wb2, const float* bb2,
                        const float* Wl, const float* bl)
{
    int tid = blockIdx.x * blockDim.x + threadIdx.x;
    {
        int k = tid >> 7, c4 = (tid & 127) * 4;
        float4 v;
        if (c4 < 256) v = *((const float4*)&Wc1[k * 256 + c4]);
        else          v = *((const float4*)&Wb1[k * 256 + (c4 - 256)]);
        *((float4*)&g_Wf[k * 512 + c4]) = v;
    }
    if (tid < 512) g_bf[tid] = (tid < 256) ? bc1[tid] : bb1[tid - 256];
    if (tid >= 512 && tid < 1024) {
        int cidx = tid - 512;
        const float* W2 = (cidx < 256) ? Wc2 : Wb2;
        int k = cidx & 255;
        float s = 0.f;
        for (int d = 0; d < 128; d++) s += W2[k * 128 + d] * Wl[d];
        g_w2l[cidx] = s;
    }
    if (tid >= 1024 && tid < 1536) {
        int cidx = tid - 1024; int u = cidx >> 8, j = cidx & 255;
        float s = 0.f;
        for (int d = 0; d < 128; d++) s += E_lab[u * 128 + d] * Wb1[(256 + d) * 256 + j];
        g_emb[u * HH + j] = s;
    }
    if (tid == 1536 || tid == 1537) {
        int u = tid - 1536;
        const float* b2 = u ? bb2 : bc2;
        float s = bl[0];
        for (int d = 0; d < 128; d++) s += b2[d] * Wl[d];
        g_pbias[u] = s;
    }
}

extern "C" void kernel_launch(void* const* d_in, const int* in_sizes, int n_in,
                              void* d_out, int out_size)
{
    const int*   info_bits = (const int*)  d_in[0];
    const float* r_in      = (const float*)d_in[1];
    const int*   info_set  = (const int*)  d_in[2];
    const float* E_obs     = (const float*)d_in[3];
    const float* E_lab     = (const float*)d_in[4];
    const float* Wc1 = (const float*)d_in[5];
    const float* bc1 = (const float*)d_in[6];
    const float* Wc2 = (const float*)d_in[7];
    const float* bc2 = (const float*)d_in[8];
    const float* Wb1 = (const float*)d_in[9];
    const float* bb1 = (const float*)d_in[10];
    const float* Wb2 = (const float*)d_in[11];
    const float* bb2 = (const float*)d_in[12];
    const float* Wl  = (const float*)d_in[13];
    const float* bl  = (const float*)d_in[14];
    float* out = (float*)d_out;

    const int smem = (8192 * 3 + 2048) * 8 + 64;   // ~208 KB
    cudaFuncSetAttribute(sc_main, cudaFuncAttributeMaxDynamicSharedMemorySize, smem);

    sc_prep<<<64, 512>>>(Wc1, bc1, Wb1, bb1, E_lab, Wc2, bc2, Wb2, bb2, Wl, bl);
    sc_setup<<<BATCH, 256>>>(info_bits, r_in, info_set, E_obs, out);
    sc_main<<<BATCH, THREADS, smem>>>(r_in, Wc2, bc2, Wb2, bb2, out);
}

// round 9
// speedup vs baseline: 1.3239x; 1.3215x over previous
#include <cuda_runtime.h>
#include <math.h>

#define BATCH   128
#define DD      128
#define HH      256
#define NBLK_C  256
#define THREADS 1024
#define SEC     (BATCH*NBLK_C)

typedef unsigned long long u64;

// ---- device scratch ----
__device__ __align__(16) float g_E[BATCH * 511 * DD];
__device__ __align__(16) float g_BP[BATCH * 255 * HH];
__device__ int   g_X[BATCH * 511];
__device__ int   g_U1H[BATCH * 256];
__device__ int   g_fenc[BATCH * NBLK_C];
__device__ __align__(16) float g_Wf[256 * 512];   // [Wc1 | Wb1-top] col-fused
__device__ __align__(16) float g_bf[512];         // [bc1 | bb1]
__device__ __align__(16) float g_emb[2 * HH];     // E_lab[u] @ Wb1[256:384,:]
__device__ __align__(16) float g_w2l[512];        // [Wc2@Wl | Wb2@Wl]
__device__ float g_pbias[2];

// ---- f32x2 helpers ----
__device__ __forceinline__ void fma2(u64& acc, u64 a, u64 b) {
    asm("fma.rn.f32x2 %0, %1, %2, %0;" : "+l"(acc) : "l"(a), "l"(b));
}
__device__ __forceinline__ u64 pk2(float x, float y) {
    u64 r; asm("mov.b64 %0, {%1, %2};" : "=l"(r) : "f"(x), "f"(y)); return r;
}
__device__ __forceinline__ float2 upk(u64 v) {
    float2 r; asm("mov.b64 {%0, %1}, %2;" : "=f"(r.x), "=f"(r.y) : "l"(v)); return r;
}

struct Ctx {
    u64* zs; u64* hs; u64* redu; float* redf;
    float* nh2; float* nbp2; float* red2; int* nx;
    const float* Wc2; const float* bc2;
    const float* Wb2; const float* bb2;
    const float* r_in;
    float* u_out; float* p_out;
    int b0;     // first of the two batches this CTA owns
};

// ---------- fused layer 1: [RB rows x 256] @ [256 x 512] ----------
// rows = [batch0 rows | batch1 rows] for level l, chunk offset 'done'.
// cols 0..255 -> relu -> hs (dup f32x2); cols 256..511 -> g_BP.
template<int RB>
__device__ void l1_chunk2(Ctx& c, int l, int done)
{
    const int t = threadIdx.x;
    const int half = 1 << (l - 1);
    const int inbase = (1 << l) - 1;
    const int bpbase = half - 1;
    // stage acts (gathered per batch), duplicated for f32x2
    for (int idx = t; idx < RB * 128; idx += THREADS) {
        int r = idx >> 7, p2 = idx & 127;
        int gr = done + r;
        int bsel = gr >= half;
        int b = c.b0 + bsel;
        int rib = gr - (bsel ? half : 0);
        float2 v = *((const float2*)(g_E + (size_t)b * 511 * DD + inbase * DD + rib * 256) + p2);
        ulonglong2 d; d.x = pk2(v.x, v.x); d.y = pk2(v.y, v.y);
        ((ulonglong2*)c.zs)[idx] = d;
    }
    __syncthreads();
    if constexpr (RB >= 8) {
        constexpr int NR = RB / 8;
        const int colq = t & 127;
        const int rg   = t >> 7;
        u64 acc[NR][2];
        #pragma unroll
        for (int r = 0; r < NR; r++) { acc[r][0] = 0ull; acc[r][1] = 0ull; }
        const ulonglong2* W = (const ulonglong2*)g_Wf + colq;
        #pragma unroll 2
        for (int k = 0; k < 256; k += 2) {
            ulonglong2 a2[NR];
            #pragma unroll
            for (int r = 0; r < NR; r++)
                a2[r] = *((const ulonglong2*)&c.zs[(rg + 8 * r) * 256 + k]);
            ulonglong2 w0 = __ldg(W + (size_t)k * 128);
            ulonglong2 w1 = __ldg(W + (size_t)(k + 1) * 128);
            #pragma unroll
            for (int r = 0; r < NR; r++) {
                fma2(acc[r][0], a2[r].x, w0.x); fma2(acc[r][1], a2[r].x, w0.y);
                fma2(acc[r][0], a2[r].y, w1.x); fma2(acc[r][1], a2[r].y, w1.y);
            }
        }
        const int col = colq * 4;
        float4 bias = *((const float4*)&g_bf[col]);
        #pragma unroll
        for (int r = 0; r < NR; r++) {
            int row = rg + 8 * r;
            float2 v0 = upk(acc[r][0]); float2 v1 = upk(acc[r][1]);
            float o0 = v0.x + bias.x, o1 = v0.y + bias.y;
            float o2 = v1.x + bias.z, o3 = v1.y + bias.w;
            if (col < 256) {
                float r0 = fmaxf(o0, 0.f), r1 = fmaxf(o1, 0.f);
                float r2 = fmaxf(o2, 0.f), r3 = fmaxf(o3, 0.f);
                ulonglong2 d0; d0.x = pk2(r0, r0); d0.y = pk2(r1, r1);
                ulonglong2 d1; d1.x = pk2(r2, r2); d1.y = pk2(r3, r3);
                *((ulonglong2*)&c.hs[row * 256 + col])     = d0;
                *((ulonglong2*)&c.hs[row * 256 + col + 2]) = d1;
            } else {
                int gr = done + row;
                int bsel = gr >= half;
                int b = c.b0 + bsel;
                int rib = gr - (bsel ? half : 0);
                *((float4*)&g_BP[(size_t)b * 255 * HH + (bpbase + rib) * HH + (col - 256)]) =
                    make_float4(o0, o1, o2, o3);
            }
        }
    } else {
        // RB == 4: split-K 2-way so all 1024 threads stream weights
        const int colq = t & 127;
        const int g    = t >> 7;       // 0..7 = kp*4 + r
        const int r    = g & 3;
        const int kp   = g >> 2;
        const int k0   = kp * 128;
        u64 acc0 = 0ull, acc1 = 0ull;
        const ulonglong2* W = (const ulonglong2*)g_Wf + colq;
        #pragma unroll 2
        for (int k = k0; k < k0 + 128; k += 2) {
            ulonglong2 a2 = *((const ulonglong2*)&c.zs[r * 256 + k]);
            ulonglong2 w0 = __ldg(W + (size_t)k * 128);
            ulonglong2 w1 = __ldg(W + (size_t)(k + 1) * 128);
            fma2(acc0, a2.x, w0.x); fma2(acc1, a2.x, w0.y);
            fma2(acc0, a2.y, w1.x); fma2(acc1, a2.y, w1.y);
        }
        ulonglong2 st; st.x = acc0; st.y = acc1;
        ((ulonglong2*)c.redu)[g * 128 + colq] = st;
        __syncthreads();
        for (int idx = t; idx < 4 * 512; idx += THREADS) {
            int row = idx >> 9, col = idx & 511;
            float v = g_bf[col] + c.redf[row * 512 + col] + c.redf[(4 + row) * 512 + col];
            if (col < 256) {
                float rl = fmaxf(v, 0.f);
                c.hs[row * 256 + col] = pk2(rl, rl);
            } else {
                int gr = done + row;
                int bsel = gr >= half;
                int b = c.b0 + bsel;
                int rib = gr - (bsel ? half : 0);
                g_BP[(size_t)b * 255 * HH + (bpbase + rib) * HH + (col - 256)] = v;
            }
        }
    }
    __syncthreads();
}

// ---------- layer 2: [RB x 256] @ [256 x 128] + b2, output -> g_E level l-1 ----------
template<int RB>
__device__ void l2_chunk2(Ctx& c, bool isBit, int l, int done)
{
    const int t = threadIdx.x;
    const int half = 1 << (l - 1);
    const int outbase = half - 1;
    const float* W2 = isBit ? c.Wb2 : c.Wc2;
    const float* b2 = isBit ? c.bb2 : c.bc2;
    const int colq = t & 31;
    const int g    = t >> 5;
    const ulonglong2* W = (const ulonglong2*)W2 + colq;
    if constexpr (RB == 32) {
        const int row = g;
        u64 acc0 = 0ull, acc1 = 0ull;
        #pragma unroll 2
        for (int k = 0; k < 256; k += 2) {
            ulonglong2 a2 = *((const ulonglong2*)&c.hs[row * 256 + k]);
            ulonglong2 w0 = __ldg(W + (size_t)k * 32);
            ulonglong2 w1 = __ldg(W + (size_t)(k + 1) * 32);
            fma2(acc0, a2.x, w0.x); fma2(acc1, a2.x, w0.y);
            fma2(acc0, a2.y, w1.x); fma2(acc1, a2.y, w1.y);
        }
        float2 v0 = upk(acc0), v1 = upk(acc1);
        const int col = colq * 4;
        float4 bb = *((const float4*)&b2[col]);
        int gr = done + row;
        int bsel = gr >= half;
        int b = c.b0 + bsel;
        int rib = gr - (bsel ? half : 0);
        *((float4*)&g_E[(size_t)b * 511 * DD + (outbase + rib) * DD + col]) =
            make_float4(v0.x + bb.x, v0.y + bb.y, v1.x + bb.z, v1.y + bb.w);
        __syncthreads();
    } else {
        constexpr int KP = 32 / RB;
        constexpr int KL = 256 / KP;
        const int row = g & (RB - 1);
        const int kp  = g / RB;
        const int k0  = kp * KL;
        u64 acc0 = 0ull, acc1 = 0ull;
        #pragma unroll 2
        for (int k = k0; k < k0 + KL; k += 2) {
            ulonglong2 a2 = *((const ulonglong2*)&c.hs[row * 256 + k]);
            ulonglong2 w0 = __ldg(W + (size_t)k * 32);
            ulonglong2 w1 = __ldg(W + (size_t)(k + 1) * 32);
            fma2(acc0, a2.x, w0.x); fma2(acc1, a2.x, w0.y);
            fma2(acc0, a2.y, w1.x); fma2(acc1, a2.y, w1.y);
        }
        ulonglong2 st; st.x = acc0; st.y = acc1;
        ((ulonglong2*)c.redu)[g * 32 + colq] = st;
        __syncthreads();
        for (int idx = t; idx < RB * 128; idx += THREADS) {
            int row2 = idx >> 7, col = idx & 127;
            float v = __ldg(&b2[col]);
            #pragma unroll
            for (int q = 0; q < KP; q++) v += c.redf[(q * RB + row2) * 128 + col];
            int gr = done + row2;
            int bsel = gr >= half;
            int b = c.b0 + bsel;
            int rib = gr - (bsel ? half : 0);
            g_E[(size_t)b * 511 * DD + (outbase + rib) * DD + col] = v;
        }
        __syncthreads();
    }
}

__device__ void check2(Ctx& c, int l)
{
    const int R = 2 << (l - 1);
    for (int done = 0; done < R; done += 32) {
        int rbc = R - done; if (rbc > 32) rbc = 32;
        switch (rbc) {
            case 32: l1_chunk2<32>(c, l, done); l2_chunk2<32>(c, false, l, done); break;
            case 16: l1_chunk2<16>(c, l, done); l2_chunk2<16>(c, false, l, done); break;
            case 8:  l1_chunk2<8 >(c, l, done); l2_chunk2<8 >(c, false, l, done); break;
            default: l1_chunk2<4 >(c, l, done); l2_chunk2<4 >(c, false, l, done); break;
        }
    }
}

__device__ void bit2(Ctx& c, int l)
{
    const int t = threadIdx.x;
    const int half = 1 << (l - 1);
    const int base = half - 1;
    const int R = 2 * half;
    __syncthreads();
    for (int i = t; i < R; i += THREADS) {
        int bsel = i >= half;
        int b = c.b0 + bsel;
        int rib = i - (bsel ? half : 0);
        g_U1H[b * 256 + base + rib] = g_X[b * 511 + base + rib];
    }
    __syncthreads();
    for (int done = 0; done < R; done += 32) {
        int rbc = R - done; if (rbc > 32) rbc = 32;
        for (int idx = t; idx < rbc * 256; idx += THREADS) {
            int r = idx >> 8, k = idx & 255;
            int gr = done + r;
            int bsel = gr >= half;
            int b = c.b0 + bsel;
            int rib = gr - (bsel ? half : 0);
            int u = g_U1H[b * 256 + base + rib];
            float v = fmaxf(g_BP[(size_t)b * 255 * HH + (base + rib) * HH + k] + g_emb[u * HH + k], 0.f);
            c.hs[r * 256 + k] = pk2(v, v);
        }
        __syncthreads();
        switch (rbc) {
            case 32: l2_chunk2<32>(c, true, l, done); break;
            case 16: l2_chunk2<16>(c, true, l, done); break;
            case 8:  l2_chunk2<8 >(c, true, l, done); break;
            default: l2_chunk2<4 >(c, true, l, done); break;
        }
    }
}

__device__ __forceinline__ void combine2(Ctx& c, int l)
{
    const int half = 1 << (l - 1);
    const int R = 2 * half;
    __syncthreads();
    for (int i = threadIdx.x; i < R; i += THREADS) {
        int bsel = i >= half;
        int b = c.b0 + bsel;
        int rib = i - (bsel ? half : 0);
        int* U  = g_U1H + b * 256 + (half - 1);
        int* Xm = g_X + b * 511 + (half - 1);
        int* Xl = g_X + b * 511 + ((1 << l) - 1);
        int u2 = Xm[rib];
        Xl[2 * rib]     = U[rib] ^ u2;
        Xl[2 * rib + 1] = u2;
    }
    __syncthreads();
}

// level-1 node for both batches: fused L1 + leaf dots vs precomputed W2@Wl
__device__ void node1(Ctx& c, int n)
{
    const int t = threadIdx.x;
    {
        const int colq = t & 127;
        const int g = t >> 7;      // 0..7 = kp*2 + r
        const int r = g & 1;       // batch select
        const int kp = g >> 1;     // 0..3
        const int k0 = kp * 64;
        const float* Ein = g_E + (size_t)(c.b0 + r) * 511 * DD + DD;  // level-1 rows
        u64 acc0 = 0ull, acc1 = 0ull;
        const ulonglong2* W = (const ulonglong2*)g_Wf + colq;
        #pragma unroll 4
        for (int kb = 0; kb < 64; kb += 4) {
            float4 a4 = __ldg((const float4*)&Ein[k0 + kb]);
            ulonglong2 w; u64 a;
            w = __ldg(W + (size_t)(k0 + kb + 0) * 128); a = pk2(a4.x, a4.x); fma2(acc0, a, w.x); fma2(acc1, a, w.y);
            w = __ldg(W + (size_t)(k0 + kb + 1) * 128); a = pk2(a4.y, a4.y); fma2(acc0, a, w.x); fma2(acc1, a, w.y);
            w = __ldg(W + (size_t)(k0 + kb + 2) * 128); a = pk2(a4.z, a4.z); fma2(acc0, a, w.x); fma2(acc1, a, w.y);
            w = __ldg(W + (size_t)(k0 + kb + 3) * 128); a = pk2(a4.w, a4.w); fma2(acc0, a, w.x); fma2(acc1, a, w.y);
        }
        ulonglong2 st; st.x = acc0; st.y = acc1;
        ((ulonglong2*)c.redu)[g * 128 + colq] = st;
    }
    __syncthreads();
    for (int idx = t; idx < 1024; idx += THREADS) {
        int r = idx >> 9, col = idx & 511;
        float v = g_bf[col];
        #pragma unroll
        for (int kp = 0; kp < 4; kp++) v += c.redf[((kp << 1) | r) * 512 + col];
        if (col < 256) c.nh2[r * 256 + col] = fmaxf(v, 0.f);
        else           c.nbp2[r * 256 + (col - 256)] = v;
    }
    __syncthreads();
    if (t < 64) {
        int w = t >> 5, lane = t & 31;
        float s = 0.f;
        #pragma unroll
        for (int j = 0; j < 8; j++) {
            int idx = lane + 32 * j;
            s = fmaf(c.nh2[w * 256 + idx], g_w2l[idx], s);
        }
        #pragma unroll
        for (int o = 16; o > 0; o >>= 1) s += __shfl_xor_sync(0xffffffffu, s, o);
        if (lane == 0) {
            int b = c.b0 + w;
            float p = 1.f / (1.f + expf(-(s + g_pbias[0])));
            int leaf = 2 * n;
            float rv = __ldg(&c.r_in[b * NBLK_C + leaf]);
            int f  = g_fenc[b * NBLK_C + leaf];
            int hd = (rv > p) ? 1 : 0;
            int x  = ((f == 2) || (fabsf(p - 0.5f) > 0.25f)) ? hd : f;
            c.nx[w] = x;
            c.u_out[b * NBLK_C + leaf] = (float)x;
            c.p_out[b * NBLK_C + leaf] = p;
        }
    }
    __syncthreads();
    for (int idx = t; idx < 512; idx += THREADS) {
        int w = idx >> 8, j = idx & 255;
        float h = fmaxf(c.nbp2[w * 256 + j] + g_emb[c.nx[w] * HH + j], 0.f);
        c.red2[idx] = h * g_w2l[256 + j];
    }
    __syncthreads();
    if (t < 64) {
        int w = t >> 5, lane = t & 31;
        float s = 0.f;
        #pragma unroll
        for (int j = 0; j < 8; j++) s += c.red2[w * 256 + lane + 32 * j];
        #pragma unroll
        for (int o = 16; o > 0; o >>= 1) s += __shfl_xor_sync(0xffffffffu, s, o);
        if (lane == 0) {
            int b = c.b0 + w;
            float p = 1.f / (1.f + expf(-(s + g_pbias[1])));
            int leaf = 2 * n + 1;
            float rv = __ldg(&c.r_in[b * NBLK_C + leaf]);
            int f  = g_fenc[b * NBLK_C + leaf];
            int hd = (rv > p) ? 1 : 0;
            int xR = ((f == 2) || (fabsf(p - 0.5f) > 0.25f)) ? hd : f;
            int xL = c.nx[w];
            c.u_out[b * NBLK_C + leaf] = (float)xR;
            c.p_out[b * NBLK_C + leaf] = p;
            g_X[b * 511 + 1] = xL ^ xR;
            g_X[b * 511 + 2] = xR;
        }
    }
    __syncthreads();
}

__global__ void __launch_bounds__(THREADS, 1)
sc_main(const float* r_in,
        const float* Wc2, const float* bc2,
        const float* Wb2, const float* bb2,
        float* out)
{
    extern __shared__ __align__(16) char smraw[];
    Ctx c;
    c.zs   = (u64*)smraw;            // 64 KB
    c.hs   = c.zs + 8192;            // 64 KB
    c.redu = c.hs + 8192;            // 16 KB
    c.redf = (float*)c.redu;
    c.nh2  = (float*)(c.redu + 2048);   // 2 KB
    c.nbp2 = c.nh2 + 512;               // 2 KB
    c.red2 = c.nbp2 + 512;              // 2 KB
    c.nx   = (int*)(c.red2 + 512);
    c.b0 = blockIdx.x * 2;
    c.Wc2 = Wc2; c.bc2 = bc2; c.Wb2 = Wb2; c.bb2 = bb2;
    c.r_in  = r_in;
    c.u_out = out + 2 * SEC;
    c.p_out = out + 3 * SEC;

    for (int l = 8; l >= 2; l--) check2(c, l);
    for (int n = 0; n < 128; n++) {
        node1(c, n);
        if (n == 127) break;
        int l = 2;
        while ((n >> (l - 2)) & 1) { combine2(c, l); l++; }
        bit2(c, l);
        for (int ld = l - 1; ld >= 2; ld--) check2(c, ld);
    }
    for (int l = 2; l <= 8; l++) combine2(c, l);

    for (int i = threadIdx.x; i < 512; i += THREADS) {
        int bsel = i >= 256;
        int b = c.b0 + bsel;
        int j = i & 255;
        out[b * NBLK_C + j] = (float)g_X[b * 511 + 255 + j];
    }
}

// ---- per-batch init ----
__global__ void sc_setup(const int* info_bits, const float* r_in, const int* info_set,
                         const float* E_obs, float* out)
{
    int b = blockIdx.x, t = threadIdx.x;
    for (int j = t; j < NBLK_C; j += blockDim.x) {
        g_fenc[b * NBLK_C + j] = 2;
        out[1 * SEC + b * NBLK_C + j] = 1.0f;
        out[4 * SEC + b * NBLK_C + j] = r_in[b * NBLK_C + j];
    }
    __syncthreads();
    for (int k = t; k < 128; k += blockDim.x) {
        int pos = info_set[k];
        g_fenc[b * NBLK_C + pos] = info_bits[b * 128 + k];
        out[1 * SEC + b * NBLK_C + pos] = 2.0f;
    }
    for (int idx = t; idx < 256 * DD; idx += blockDim.x) {
        int i = idx >> 7, k = idx & (DD - 1);
        g_E[(size_t)b * 511 * DD + (255 + i) * DD + k] = E_obs[2 * DD + k];
    }
}

// ---- parallel weight prep ----
__global__ void sc_prep(const float* Wc1, const float* bc1,
                        const float* Wb1, const float* bb1,
                        const float* E_lab,
                        const float* Wc2, const float* bc2,
                        const float* Wb2, const float* bb2,
                        const float* Wl, const float* bl)
{
    int tid = blockIdx.x * blockDim.x + threadIdx.x;   // 64*512
    {
        int k = tid >> 7, c4 = (tid & 127) * 4;
        float4 v;
        if (c4 < 256) v = *((const float4*)&Wc1[k * 256 + c4]);
        else          v = *((const float4*)&Wb1[k * 256 + (c4 - 256)]);
        *((float4*)&g_Wf[k * 512 + c4]) = v;
    }
    if (tid < 512) g_bf[tid] = (tid < 256) ? bc1[tid] : bb1[tid - 256];
    if (tid >= 512 && tid < 1024) {
        int cidx = tid - 512;
        const float* W2 = (cidx < 256) ? Wc2 : Wb2;
        int k = cidx & 255;
        float s = 0.f;
        for (int d = 0; d < 128; d++) s += W2[k * 128 + d] * Wl[d];
        g_w2l[cidx] = s;
    }
    if (tid >= 1024 && tid < 1536) {
        int cidx = tid - 1024; int u = cidx >> 8, j = cidx & 255;
        float s = 0.f;
        for (int d = 0; d < 128; d++) s += E_lab[u * 128 + d] * Wb1[(256 + d) * 256 + j];
        g_emb[u * HH + j] = s;
    }
    if (tid == 1536 || tid == 1537) {
        int u = tid - 1536;
        const float* b2 = u ? bb2 : bc2;
        float s = bl[0];
        for (int d = 0; d < 128; d++) s += b2[d] * Wl[d];
        g_pbias[u] = s;
    }
}

extern "C" void kernel_launch(void* const* d_in, const int* in_sizes, int n_in,
                              void* d_out, int out_size)
{
    const int*   info_bits = (const int*)  d_in[0];
    const float* r_in      = (const float*)d_in[1];
    const int*   info_set  = (const int*)  d_in[2];
    const float* E_obs     = (const float*)d_in[3];
    const float* E_lab     = (const float*)d_in[4];
    const float* Wc1 = (const float*)d_in[5];
    const float* bc1 = (const float*)d_in[6];
    const float* Wc2 = (const float*)d_in[7];
    const float* bc2 = (const float*)d_in[8];
    const float* Wb1 = (const float*)d_in[9];
    const float* bb1 = (const float*)d_in[10];
    const float* Wb2 = (const float*)d_in[11];
    const float* bb2 = (const float*)d_in[12];
    const float* Wl  = (const float*)d_in[13];
    const float* bl  = (const float*)d_in[14];
    float* out = (float*)d_out;

    const int smem = 8192 * 8 * 2 + 2048 * 8 + (512 * 3) * 4 + 16;   // ~150 KB
    cudaFuncSetAttribute(sc_main, cudaFuncAttributeMaxDynamicSharedMemorySize, smem);

    sc_prep<<<64, 512>>>(Wc1, bc1, Wb1, bb1, E_lab, Wc2, bc2, Wb2, bb2, Wl, bl);
    sc_setup<<<BATCH, 256>>>(info_bits, r_in, info_set, E_obs, out);
    sc_main<<<64, THREADS, smem>>>(r_in, Wc2, bc2, Wb2, bb2, out);
}

// round 10
// speedup vs baseline: 2.4267x; 1.8330x over previous
#include <cuda_runtime.h>
#include <math.h>

#define BATCH   128
#define DD      128
#define HH      256
#define NBLK_C  256
#define THREADS 1024
#define RBMAX   32
#define KC      64          // k-rows of Wf cached in smem
#define SEC     (BATCH*NBLK_C)

typedef unsigned long long u64;

// ---- device scratch ----
__device__ __align__(16) float g_E[BATCH * 511 * DD];
__device__ __align__(16) float g_BP[BATCH * 255 * HH];
__device__ int   g_X[BATCH * 511];
__device__ int   g_U1H[BATCH * 256];
__device__ int   g_fenc[BATCH * NBLK_C];
__device__ __align__(16) float g_Wf[256 * 512];   // [Wc1 | Wb1-top] col-fused
__device__ __align__(16) float g_bf[512];         // [bc1 | bb1]
__device__ __align__(16) float g_emb[2 * HH];     // E_lab[u] @ Wb1[256:384,:]
__device__ __align__(16) float g_w2l[512];        // [Wc2@Wl | Wb2@Wl]
__device__ float g_pbias[2];

// ---- f32x2 helpers ----
__device__ __forceinline__ void fma2(u64& acc, u64 a, u64 b) {
    asm("fma.rn.f32x2 %0, %1, %2, %0;" : "+l"(acc) : "l"(a), "l"(b));
}
__device__ __forceinline__ u64 pk2(float x, float y) {
    u64 r; asm("mov.b64 %0, {%1, %2};" : "=l"(r) : "f"(x), "f"(y)); return r;
}
__device__ __forceinline__ float2 upk(u64 v) {
    float2 r; asm("mov.b64 {%0, %1}, %2;" : "=f"(r.x), "=f"(r.y) : "l"(v)); return r;
}

struct Ctx {
    float* Eb; float* BPb; int* Xb; int* U1Hb;
    float* sWf;            // smem: Wf rows [0,KC) full width (128 KB)
    float* zs; float* hs;  // f32 (not duplicated)
    u64* redu; float* redf;
    float* nh; float* nbp; int* nx;
    const float* Wc2; const float* bc2;
    const float* Wb2; const float* bb2;
    const float* r_in;
    float* u_out; float* p_out;
    int b;
};

// ---------- fused layer 1: [RB x 256] @ [256 x 512] ----------
template<int RB>
__device__ void l1_chunk(Ctx& c, const float* __restrict__ Ein, float* __restrict__ bp_out)
{
    const int t = threadIdx.x;
    if constexpr (RB >= 8) {
        // stage acts as f32
        {
            const float4* src = (const float4*)Ein;
            float4* dst = (float4*)c.zs;
            for (int i = t; i < RB * 64; i += THREADS) dst[i] = src[i];
        }
        __syncthreads();
        constexpr int NR = RB / 8;
        const int colq = t & 127;
        const int rg   = t >> 7;
        u64 acc[NR][2];
        #pragma unroll
        for (int r = 0; r < NR; r++) { acc[r][0] = 0ull; acc[r][1] = 0ull; }
        const ulonglong2* Ws = (const ulonglong2*)c.sWf + colq;
        const ulonglong2* Wg = (const ulonglong2*)g_Wf + colq;
        #pragma unroll 2
        for (int k = 0; k < KC; k += 2) {
            ulonglong2 w0 = Ws[(size_t)k * 128];
            ulonglong2 w1 = Ws[(size_t)(k + 1) * 128];
            #pragma unroll
            for (int r = 0; r < NR; r++) {
                float2 a = *((const float2*)&c.zs[(rg + 8 * r) * 256 + k]);
                u64 ax = pk2(a.x, a.x), ay = pk2(a.y, a.y);
                fma2(acc[r][0], ax, w0.x); fma2(acc[r][1], ax, w0.y);
                fma2(acc[r][0], ay, w1.x); fma2(acc[r][1], ay, w1.y);
            }
        }
        #pragma unroll 2
        for (int k = KC; k < 256; k += 2) {
            ulonglong2 w0 = __ldg(Wg + (size_t)k * 128);
            ulonglong2 w1 = __ldg(Wg + (size_t)(k + 1) * 128);
            #pragma unroll
            for (int r = 0; r < NR; r++) {
                float2 a = *((const float2*)&c.zs[(rg + 8 * r) * 256 + k]);
                u64 ax = pk2(a.x, a.x), ay = pk2(a.y, a.y);
                fma2(acc[r][0], ax, w0.x); fma2(acc[r][1], ax, w0.y);
                fma2(acc[r][0], ay, w1.x); fma2(acc[r][1], ay, w1.y);
            }
        }
        const int col = colq * 4;
        float4 bias = *((const float4*)&g_bf[col]);
        #pragma unroll
        for (int r = 0; r < NR; r++) {
            int row = rg + 8 * r;
            float2 v0 = upk(acc[r][0]); float2 v1 = upk(acc[r][1]);
            float o0 = v0.x + bias.x, o1 = v0.y + bias.y;
            float o2 = v1.x + bias.z, o3 = v1.y + bias.w;
            if (col < 256) {
                *((float4*)&c.hs[row * 256 + col]) =
                    make_float4(fmaxf(o0, 0.f), fmaxf(o1, 0.f), fmaxf(o2, 0.f), fmaxf(o3, 0.f));
            } else {
                *((float4*)&bp_out[row * HH + (col - 256)]) = make_float4(o0, o1, o2, o3);
            }
        }
        __syncthreads();
    } else {
        // RB = 2 or 4: split-K, acts direct from global
        constexpr int KP = 8 / RB;
        constexpr int KL = 256 / KP;
        const int colq = t & 127;
        const int g    = t >> 7;
        const int r    = g & (RB - 1);
        const int kp   = g / RB;
        const int k0   = kp * KL;
        const float* ac = Ein + r * 256;
        u64 acc0 = 0ull, acc1 = 0ull;
        const ulonglong2* Ws = (const ulonglong2*)c.sWf + colq;
        const ulonglong2* Wg = (const ulonglong2*)g_Wf + colq;
        int ksm = (k0 + KL < KC) ? (k0 + KL) : KC;      // smem segment end
        for (int k = k0; k < ksm; k += 4) {
            float4 a4 = __ldg((const float4*)&ac[k]);
            ulonglong2 w; u64 a;
            w = Ws[(size_t)(k + 0) * 128]; a = pk2(a4.x, a4.x); fma2(acc0, a, w.x); fma2(acc1, a, w.y);
            w = Ws[(size_t)(k + 1) * 128]; a = pk2(a4.y, a4.y); fma2(acc0, a, w.x); fma2(acc1, a, w.y);
            w = Ws[(size_t)(k + 2) * 128]; a = pk2(a4.z, a4.z); fma2(acc0, a, w.x); fma2(acc1, a, w.y);
            w = Ws[(size_t)(k + 3) * 128]; a = pk2(a4.w, a4.w); fma2(acc0, a, w.x); fma2(acc1, a, w.y);
        }
        int kgl = (k0 > KC) ? k0 : KC;                  // global segment start
        #pragma unroll 2
        for (int k = kgl; k < k0 + KL; k += 4) {
            float4 a4 = __ldg((const float4*)&ac[k]);
            ulonglong2 w; u64 a;
            w = __ldg(Wg + (size_t)(k + 0) * 128); a = pk2(a4.x, a4.x); fma2(acc0, a, w.x); fma2(acc1, a, w.y);
            w = __ldg(Wg + (size_t)(k + 1) * 128); a = pk2(a4.y, a4.y); fma2(acc0, a, w.x); fma2(acc1, a, w.y);
            w = __ldg(Wg + (size_t)(k + 2) * 128); a = pk2(a4.z, a4.z); fma2(acc0, a, w.x); fma2(acc1, a, w.y);
            w = __ldg(Wg + (size_t)(k + 3) * 128); a = pk2(a4.w, a4.w); fma2(acc0, a, w.x); fma2(acc1, a, w.y);
        }
        float2 v0 = upk(acc0), v1 = upk(acc1);
        ((float4*)c.redf)[g * 128 + colq] = make_float4(v0.x, v0.y, v1.x, v1.y);
        __syncthreads();
        for (int idx = t; idx < RB * 512; idx += THREADS) {
            int row = idx >> 9, col = idx & 511;
            float v = g_bf[col];
            #pragma unroll
            for (int q = 0; q < KP; q++) v += c.redf[(q * RB + row) * 512 + col];
            if (col < 256) c.hs[row * 256 + col] = fmaxf(v, 0.f);
            else bp_out[row * HH + (col - 256)] = v;
        }
        __syncthreads();
    }
}

// ---------- layer 2: [RB x 256] @ [256 x 128] + b2 ----------
template<int RB>
__device__ void l2_chunk(Ctx& c, const float* __restrict__ W2,
                         const float* __restrict__ b2, float* __restrict__ Eout)
{
    const int t = threadIdx.x;
    const int colq = t & 31;
    const int g    = t >> 5;
    const ulonglong2* W = (const ulonglong2*)W2 + colq;
    if constexpr (RB == 32) {
        const int row = g;
        u64 acc0 = 0ull, acc1 = 0ull;
        #pragma unroll 2
        for (int k = 0; k < 256; k += 2) {
            float2 h = *((const float2*)&c.hs[row * 256 + k]);
            u64 ax = pk2(h.x, h.x), ay = pk2(h.y, h.y);
            ulonglong2 w0 = __ldg(W + (size_t)k * 32);
            ulonglong2 w1 = __ldg(W + (size_t)(k + 1) * 32);
            fma2(acc0, ax, w0.x); fma2(acc1, ax, w0.y);
            fma2(acc0, ay, w1.x); fma2(acc1, ay, w1.y);
        }
        float2 v0 = upk(acc0), v1 = upk(acc1);
        const int col = colq * 4;
        float4 bb = *((const float4*)&b2[col]);
        *((float4*)&Eout[row * 128 + col]) =
            make_float4(v0.x + bb.x, v0.y + bb.y, v1.x + bb.z, v1.y + bb.w);
        __syncthreads();
    } else {
        constexpr int KP = 32 / RB;
        constexpr int KL = 256 / KP;
        const int row = g & (RB - 1);
        const int kp  = g / RB;
        const int k0  = kp * KL;
        u64 acc0 = 0ull, acc1 = 0ull;
        #pragma unroll 2
        for (int k = k0; k < k0 + KL; k += 2) {
            float2 h = *((const float2*)&c.hs[row * 256 + k]);
            u64 ax = pk2(h.x, h.x), ay = pk2(h.y, h.y);
            ulonglong2 w0 = __ldg(W + (size_t)k * 32);
            ulonglong2 w1 = __ldg(W + (size_t)(k + 1) * 32);
            fma2(acc0, ax, w0.x); fma2(acc1, ax, w0.y);
            fma2(acc0, ay, w1.x); fma2(acc1, ay, w1.y);
        }
        float2 v0 = upk(acc0), v1 = upk(acc1);
        ((float4*)c.redf)[g * 32 + colq] = make_float4(v0.x, v0.y, v1.x, v1.y);
        __syncthreads();
        for (int idx = t; idx < RB * 128; idx += THREADS) {
            int row2 = idx >> 7, col = idx & 127;
            float v = __ldg(&b2[col]);
            #pragma unroll
            for (int q = 0; q < KP; q++) v += c.redf[(q * RB + row2) * 128 + col];
            Eout[row2 * 128 + col] = v;
        }
        __syncthreads();
    }
}

__device__ void check_stage(Ctx& c, int l)
{
    const int half = 1 << (l - 1);
    const float* Ein = c.Eb + ((1 << l) - 1) * DD;
    float* Eout = c.Eb + (half - 1) * DD;
    float* BPl  = c.BPb + (half - 1) * HH;
    for (int done = 0; done < half; done += RBMAX) {
        int rbc = half - done; if (rbc > RBMAX) rbc = RBMAX;
        const float* ei = Ein + done * 256;
        float* eo = Eout + done * DD;
        float* bo = BPl + done * HH;
        switch (rbc) {
            case 32: l1_chunk<32>(c, ei, bo); l2_chunk<32>(c, c.Wc2, c.bc2, eo); break;
            case 16: l1_chunk<16>(c, ei, bo); l2_chunk<16>(c, c.Wc2, c.bc2, eo); break;
            case 8:  l1_chunk<8 >(c, ei, bo); l2_chunk<8 >(c, c.Wc2, c.bc2, eo); break;
            case 4:  l1_chunk<4 >(c, ei, bo); l2_chunk<4 >(c, c.Wc2, c.bc2, eo); break;
            default: l1_chunk<2 >(c, ei, bo); l2_chunk<2 >(c, c.Wc2, c.bc2, eo); break;
        }
    }
}

__device__ void bit_stage(Ctx& c, int l)
{
    const int half = 1 << (l - 1);
    const int base = half - 1;
    float* Eout = c.Eb + base * DD;
    const float* BPl = c.BPb + base * HH;
    int* u1h = c.U1Hb + base;
    int* Xlm = c.Xb + base;
    __syncthreads();
    for (int i = threadIdx.x; i < half; i += THREADS) u1h[i] = Xlm[i];
    __syncthreads();
    for (int done = 0; done < half; done += RBMAX) {
        int rbc = half - done; if (rbc > RBMAX) rbc = RBMAX;
        for (int idx = threadIdx.x; idx < rbc * 256; idx += THREADS) {
            int row = idx >> 8, k = idx & 255;
            int u = u1h[done + row];
            c.hs[idx] = fmaxf(BPl[(done + row) * HH + k] + g_emb[u * HH + k], 0.f);
        }
        __syncthreads();
        float* eo = Eout + done * DD;
        switch (rbc) {
            case 32: l2_chunk<32>(c, c.Wb2, c.bb2, eo); break;
            case 16: l2_chunk<16>(c, c.Wb2, c.bb2, eo); break;
            case 8:  l2_chunk<8 >(c, c.Wb2, c.bb2, eo); break;
            case 4:  l2_chunk<4 >(c, c.Wb2, c.bb2, eo); break;
            default: l2_chunk<2 >(c, c.Wb2, c.bb2, eo); break;
        }
    }
}

__device__ __forceinline__ void combine_stage(Ctx& c, int l)
{
    int half = 1 << (l - 1);
    int* u1h = c.U1Hb + (half - 1);
    int* Xlm = c.Xb + (half - 1);
    int* Xl  = c.Xb + ((1 << l) - 1);
    __syncthreads();
    for (int i = threadIdx.x; i < half; i += THREADS) {
        int u2 = Xlm[i];
        Xl[2 * i]     = u1h[i] ^ u2;
        Xl[2 * i + 1] = u2;
    }
    __syncthreads();
}

// Fused level-1 node: check-L1 -> left leaf -> bit-hidden -> right leaf -> combine(1)
__device__ void node1(Ctx& c, int n)
{
    const int t = threadIdx.x;
    const float* Ein = c.Eb + DD;   // level-1 rows (2 x 128 = 256 floats)
    const int colq = t & 127;
    const int kp   = t >> 7;
    const int k0   = kp * 32;
    u64 acc0 = 0ull, acc1 = 0ull;
    if (kp < 2) {
        const ulonglong2* Ws = (const ulonglong2*)c.sWf + colq;
        #pragma unroll
        for (int kb = 0; kb < 32; kb += 4) {
            float4 a4 = __ldg((const float4*)&Ein[k0 + kb]);
            ulonglong2 w; u64 a;
            w = Ws[(size_t)(k0 + kb + 0) * 128]; a = pk2(a4.x, a4.x); fma2(acc0, a, w.x); fma2(acc1, a, w.y);
            w = Ws[(size_t)(k0 + kb + 1) * 128]; a = pk2(a4.y, a4.y); fma2(acc0, a, w.x); fma2(acc1, a, w.y);
            w = Ws[(size_t)(k0 + kb + 2) * 128]; a = pk2(a4.z, a4.z); fma2(acc0, a, w.x); fma2(acc1, a, w.y);
            w = Ws[(size_t)(k0 + kb + 3) * 128]; a = pk2(a4.w, a4.w); fma2(acc0, a, w.x); fma2(acc1, a, w.y);
        }
    } else {
        const ulonglong2* Wg = (const ulonglong2*)g_Wf + colq;
        #pragma unroll
        for (int kb = 0; kb < 32; kb += 4) {
            float4 a4 = __ldg((const float4*)&Ein[k0 + kb]);
            ulonglong2 w; u64 a;
            w = __ldg(Wg + (size_t)(k0 + kb + 0) * 128); a = pk2(a4.x, a4.x); fma2(acc0, a, w.x); fma2(acc1, a, w.y);
            w = __ldg(Wg + (size_t)(k0 + kb + 1) * 128); a = pk2(a4.y, a4.y); fma2(acc0, a, w.x); fma2(acc1, a, w.y);
            w = __ldg(Wg + (size_t)(k0 + kb + 2) * 128); a = pk2(a4.z, a4.z); fma2(acc0, a, w.x); fma2(acc1, a, w.y);
            w = __ldg(Wg + (size_t)(k0 + kb + 3) * 128); a = pk2(a4.w, a4.w); fma2(acc0, a, w.x); fma2(acc1, a, w.y);
        }
    }
    float2 v0 = upk(acc0), v1 = upk(acc1);
    ((float4*)c.redf)[kp * 128 + colq] = make_float4(v0.x, v0.y, v1.x, v1.y);
    __syncthreads();
    if (t < 512) {
        float v = g_bf[t];
        #pragma unroll
        for (int q = 0; q < 8; q++) v += c.redf[q * 512 + t];
        if (t < 256) c.nh[t] = fmaxf(v, 0.f);
        else c.nbp[t - 256] = v;
    }
    __syncthreads();
    if (t < 32) {
        float s = 0.f;
        #pragma unroll
        for (int j = 0; j < 8; j++) s = fmaf(c.nh[t + 32 * j], g_w2l[t + 32 * j], s);
        #pragma unroll
        for (int o = 16; o > 0; o >>= 1) s += __shfl_xor_sync(0xffffffffu, s, o);
        if (t == 0) {
            float p = 1.f / (1.f + expf(-(s + g_pbias[0])));
            int leaf = 2 * n;
            float rv = __ldg(&c.r_in[c.b * NBLK_C + leaf]);
            int f  = g_fenc[c.b * NBLK_C + leaf];
            int hd = (rv > p) ? 1 : 0;
            int x  = ((f == 2) || (fabsf(p - 0.5f) > 0.25f)) ? hd : f;
            *c.nx = x;
            c.u_out[c.b * NBLK_C + leaf] = (float)x;
            c.p_out[c.b * NBLK_C + leaf] = p;
        }
    }
    __syncthreads();
    int xL = *c.nx;
    if (t < 256)
        c.redf[t] = fmaxf(c.nbp[t] + g_emb[xL * HH + t], 0.f) * g_w2l[256 + t];
    __syncthreads();
    if (t < 32) {
        float s = 0.f;
        #pragma unroll
        for (int j = 0; j < 8; j++) s += c.redf[t + 32 * j];
        #pragma unroll
        for (int o = 16; o > 0; o >>= 1) s += __shfl_xor_sync(0xffffffffu, s, o);
        if (t == 0) {
            float p = 1.f / (1.f + expf(-(s + g_pbias[1])));
            int leaf = 2 * n + 1;
            float rv = __ldg(&c.r_in[c.b * NBLK_C + leaf]);
            int f  = g_fenc[c.b * NBLK_C + leaf];
            int hd = (rv > p) ? 1 : 0;
            int xR = ((f == 2) || (fabsf(p - 0.5f) > 0.25f)) ? hd : f;
            c.u_out[c.b * NBLK_C + leaf] = (float)xR;
            c.p_out[c.b * NBLK_C + leaf] = p;
            c.Xb[1] = xL ^ xR;   // combine(1)
            c.Xb[2] = xR;
        }
    }
    __syncthreads();
}

__global__ void __launch_bounds__(THREADS, 1)
sc_main(const float* r_in,
        const float* Wc2, const float* bc2,
        const float* Wb2, const float* bb2,
        float* out)
{
    extern __shared__ __align__(16) char smraw[];
    Ctx c;
    c.sWf = (float*)smraw;                 // 128 KB: Wf rows [0,KC)
    c.zs  = c.sWf + KC * 512;              // 32 KB
    c.hs  = c.zs + 32 * 256;               // 32 KB
    c.redu = (u64*)(c.hs + 32 * 256);      // 16 KB
    c.redf = (float*)c.redu;
    c.nh  = (float*)(c.redu + 2048);
    c.nbp = c.nh + 256;
    c.nx  = (int*)(c.nbp + 256);
    c.b = blockIdx.x;
    c.Eb   = g_E   + (size_t)c.b * 511 * DD;
    c.BPb  = g_BP  + (size_t)c.b * 255 * HH;
    c.Xb   = g_X   + c.b * 511;
    c.U1Hb = g_U1H + c.b * 256;
    c.Wc2 = Wc2; c.bc2 = bc2; c.Wb2 = Wb2; c.bb2 = bb2;
    c.r_in  = r_in;
    c.u_out = out + 2 * SEC;
    c.p_out = out + 3 * SEC;

    // load Wf rows [0,KC) into smem once
    {
        const float4* src = (const float4*)g_Wf;
        float4* dst = (float4*)c.sWf;
        for (int i = threadIdx.x; i < KC * 128; i += THREADS) dst[i] = src[i];
    }
    __syncthreads();

    for (int l = 8; l >= 2; l--) check_stage(c, l);
    for (int n = 0; n < 128; n++) {
        node1(c, n);
        if (n == 127) break;
        int l = 2;
        while ((n >> (l - 2)) & 1) { combine_stage(c, l); l++; }
        bit_stage(c, l);
        for (int ld = l - 1; ld >= 2; ld--) check_stage(c, ld);
    }
    for (int l = 2; l <= 8; l++) combine_stage(c, l);

    int* X8 = c.Xb + 255;
    for (int i = threadIdx.x; i < NBLK_C; i += THREADS)
        out[c.b * NBLK_C + i] = (float)X8[i];
}

// ---- merged init: per-batch setup (all 128 blocks) + weight prep (blocks 0..63) ----
__global__ void sc_init(const int* info_bits, const float* r_in, const int* info_set,
                        const float* E_obs, float* out,
                        const float* Wc1, const float* bc1,
                        const float* Wb1, const float* bb1,
                        const float* E_lab,
                        const float* Wc2, const float* bc2,
                        const float* Wb2, const float* bb2,
                        const float* Wl, const float* bl)
{
    int b = blockIdx.x, t = threadIdx.x;
    // --- setup part ---
    for (int j = t; j < NBLK_C; j += blockDim.x) {
        g_fenc[b * NBLK_C + j] = 2;
        out[1 * SEC + b * NBLK_C + j] = 1.0f;
        out[4 * SEC + b * NBLK_C + j] = r_in[b * NBLK_C + j];
    }
    __syncthreads();
    for (int k = t; k < 128; k += blockDim.x) {
        int pos = info_set[k];
        g_fenc[b * NBLK_C + pos] = info_bits[b * 128 + k];
        out[1 * SEC + b * NBLK_C + pos] = 2.0f;
    }
    for (int idx = t; idx < 256 * DD; idx += blockDim.x) {
        int i = idx >> 7, k = idx & (DD - 1);
        g_E[(size_t)b * 511 * DD + (255 + i) * DD + k] = E_obs[2 * DD + k];
    }
    // --- prep part (blocks 0..63, 512 threads each => 32768 tids) ---
    if (b < 64) {
        int tid = b * 512 + t;
        {
            int k = tid >> 7, c4 = (tid & 127) * 4;
            float4 v;
            if (c4 < 256) v = *((const float4*)&Wc1[k * 256 + c4]);
            else          v = *((const float4*)&Wb1[k * 256 + (c4 - 256)]);
            *((float4*)&g_Wf[k * 512 + c4]) = v;
        }
        if (tid < 512) g_bf[tid] = (tid < 256) ? bc1[tid] : bb1[tid - 256];
        if (tid >= 512 && tid < 1024) {
            int cidx = tid - 512;
            const float* W2 = (cidx < 256) ? Wc2 : Wb2;
            int k = cidx & 255;
            float s = 0.f;
            for (int d = 0; d < 128; d++) s += W2[k * 128 + d] * Wl[d];
            g_w2l[cidx] = s;
        }
        if (tid >= 1024 && tid < 1536) {
            int cidx = tid - 1024; int u = cidx >> 8, j = cidx & 255;
            float s = 0.f;
            for (int d = 0; d < 128; d++) s += E_lab[u * 128 + d] * Wb1[(256 + d) * 256 + j];
            g_emb[u * HH + j] = s;
        }
        if (tid == 1536 || tid == 1537) {
            int u = tid - 1536;
            const float* b2 = u ? bb2 : bc2;
            float s = bl[0];
            for (int d = 0; d < 128; d++) s += b2[d] * Wl[d];
            g_pbias[u] = s;
        }
    }
}

extern "C" void kernel_launch(void* const* d_in, const int* in_sizes, int n_in,
                              void* d_out, int out_size)
{
    const int*   info_bits = (const int*)  d_in[0];
    const float* r_in      = (const float*)d_in[1];
    const int*   info_set  = (const int*)  d_in[2];
    const float* E_obs     = (const float*)d_in[3];
    const float* E_lab     = (const float*)d_in[4];
    const float* Wc1 = (const float*)d_in[5];
    const float* bc1 = (const float*)d_in[6];
    const float* Wc2 = (const float*)d_in[7];
    const float* bc2 = (const float*)d_in[8];
    const float* Wb1 = (const float*)d_in[9];
    const float* bb1 = (const float*)d_in[10];
    const float* Wb2 = (const float*)d_in[11];
    const float* bb2 = (const float*)d_in[12];
    const float* Wl  = (const float*)d_in[13];
    const float* bl  = (const float*)d_in[14];
    float* out = (float*)d_out;

    // smem: sWf 128K + zs 32K + hs 32K + redu 16K + node buffers ~2.1K
    const int smem = (KC * 512 + 32 * 256 + 32 * 256) * 4 + 16384 + (256 + 256 + 8) * 4;
    cudaFuncSetAttribute(sc_main, cudaFuncAttributeMaxDynamicSharedMemorySize, smem);

    sc_init<<<BATCH, 512>>>(info_bits, r_in, info_set, E_obs, out,
                            Wc1, bc1, Wb1, bb1, E_lab, Wc2, bc2, Wb2, bb2, Wl, bl);
    sc_main<<<BATCH, THREADS, smem>>>(r_in, Wc2, bc2, Wb2, bb2, out);
}